// round 3
// baseline (speedup 1.0000x reference)
#include <cuda_runtime.h>
#include <cstddef>
#include <cstdint>

#define N_NODES 14
#define BATCH   4096
#define FIN     1024
#define FOUT    1024
#define HID     512
#define MROWS   (BATCH * N_NODES)        /* 57344 */

#define SZ_FINAL (MROWS * FOUT)          /* 58720256 */
#define SZ_CORR  (BATCH * N_NODES * N_NODES)
#define OFF_CORR SZ_FINAL
#define OFF_H    (OFF_CORR + SZ_CORR)

// ------------------------- device scratch -----------------------------------
__device__ float  g_A1n[196];
__device__ float  g_A2n[196];
__device__ float  g_xw1 [MROWS * HID];     // x @ gcn1_w
__device__ float  g_pre1[MROWS * HID];     // A1n @ xw1 + b1
__device__ float  g_pre3[MROWS * HID];     // A2n @ xw1 + b1
__device__ float  g_xw2a[MROWS * FOUT];    // out3 @ gcn2_w
__device__ float  g_xw2b[MROWS * FOUT];    // out  @ gcn2_w
__device__ float  g_corrn[BATCH * 196];    // normalized corr adjacency
__device__ double g_part[4 * BATCH * 14 * 2];  // per-(set,batch,node) {sum,sumsq}
__device__ float  g_scale[4][14];
__device__ float  g_shift[4][14];

__device__ __forceinline__ float lrelu(float v) { return v > 0.f ? v : 0.2f * v; }

__device__ __forceinline__ float wred(float v) {
#pragma unroll
    for (int o = 16; o; o >>= 1) v += __shfl_xor_sync(0xffffffffu, v, o);
    return v;
}

// ------------------------- adjacency prep -----------------------------------
__global__ void prep_adj(const float* __restrict__ adj1, const float* __restrict__ adj2) {
    __shared__ float a[2][196];
    __shared__ float dv[2][14];
    int t = threadIdx.x;                 // 196 threads
    int i = t / 14, j = t % 14;
    a[0][t] = (i == j) ? 1.f : adj1[t];
    a[1][t] = (i == j) ? 1.f : adj2[t];
    __syncthreads();
    if (t < 28) {
        int s = t / 14, r = t % 14;
        float acc = 0.f;
        for (int c = 0; c < 14; c++) acc += a[s][r * 14 + c];
        dv[s][r] = 1.f / sqrtf(fmaxf(acc, 1.f));
    }
    __syncthreads();
    g_A1n[t] = dv[0][i] * a[0][t] * dv[0][j];
    g_A2n[t] = dv[1][i] * a[1][t] * dv[1][j];
}

// ------------------------- SGEMM 128x128x8, double-buffered ------------------
template <int PRESET>
__device__ __forceinline__ float4 pre_xform(float4 v, float sc, float sh) {
    if (PRESET >= 0) {
        v.x = lrelu(fmaf(v.x, sc, sh));
        v.y = lrelu(fmaf(v.y, sc, sh));
        v.z = lrelu(fmaf(v.z, sc, sh));
        v.w = lrelu(fmaf(v.w, sc, sh));
    }
    return v;
}

// C[M x NTOT] = op(A[M x KTOT]) * B[KTOT x NTOT]  (+ bias, lrelu if EPI)
// PRESET >= 0 : A element -> lrelu(a * g_scale[PRESET][row%14] + g_shift[...])
template <int KTOT, int NTOT, int PRESET, bool EPI>
__global__ __launch_bounds__(256, 2)
void sgemm_k(const float* __restrict__ A, const float* __restrict__ Bm,
             const float* __restrict__ bias, float* __restrict__ C) {
    __shared__ float As[2][8][128];
    __shared__ float Bs[2][8][128];
    const int tid = threadIdx.x;
    const int bx = blockIdx.x, by = blockIdx.y;
    const int rowA = tid >> 1, kA = (tid & 1) * 4;
    const int kB = tid >> 5, colB = (tid & 31) * 4;
    const int ty = tid >> 4, tx = tid & 15;

    const float* Ap = A + (size_t)(by * 128 + rowA) * KTOT + kA;
    const float* Bp = Bm + (size_t)kB * NTOT + bx * 128 + colB;

    float psc = 1.f, psh = 0.f;
    if (PRESET >= 0) {
        int node = (by * 128 + rowA) % N_NODES;
        psc = g_scale[PRESET][node];
        psh = g_shift[PRESET][node];
    }

    float acc[8][8];
#pragma unroll
    for (int i = 0; i < 8; i++)
#pragma unroll
        for (int j = 0; j < 8; j++) acc[i][j] = 0.f;

    // preload tile 0
    float4 va = *(const float4*)Ap;
    float4 vb = *(const float4*)Bp;
    va = pre_xform<PRESET>(va, psc, psh);
    As[0][kA + 0][rowA] = va.x;
    As[0][kA + 1][rowA] = va.y;
    As[0][kA + 2][rowA] = va.z;
    As[0][kA + 3][rowA] = va.w;
    *(float4*)&Bs[0][kB][colB] = vb;
    __syncthreads();

    const int NK = KTOT / 8;
    for (int kt = 0; kt < NK; kt++) {
        const int cur = kt & 1;
        float4 na, nb;
        if (kt + 1 < NK) {
            na = *(const float4*)(Ap + (kt + 1) * 8);
            nb = *(const float4*)(Bp + (size_t)(kt + 1) * 8 * NTOT);
        }
#pragma unroll
        for (int k = 0; k < 8; k++) {
            float fa[8], fb[8];
            *(float4*)&fa[0] = *(const float4*)&As[cur][k][ty * 8];
            *(float4*)&fa[4] = *(const float4*)&As[cur][k][ty * 8 + 4];
            *(float4*)&fb[0] = *(const float4*)&Bs[cur][k][tx * 8];
            *(float4*)&fb[4] = *(const float4*)&Bs[cur][k][tx * 8 + 4];
#pragma unroll
            for (int i = 0; i < 8; i++)
#pragma unroll
                for (int j = 0; j < 8; j++) acc[i][j] = fmaf(fa[i], fb[j], acc[i][j]);
        }
        if (kt + 1 < NK) {
            na = pre_xform<PRESET>(na, psc, psh);
            As[cur ^ 1][kA + 0][rowA] = na.x;
            As[cur ^ 1][kA + 1][rowA] = na.y;
            As[cur ^ 1][kA + 2][rowA] = na.z;
            As[cur ^ 1][kA + 3][rowA] = na.w;
            *(float4*)&Bs[cur ^ 1][kB][colB] = nb;
        }
        __syncthreads();
    }

    const int crow = by * 128 + ty * 8;
    const int ccol = bx * 128 + tx * 8;
    float bv[8];
    if (EPI) {
        *(float4*)&bv[0] = *(const float4*)&bias[ccol];
        *(float4*)&bv[4] = *(const float4*)&bias[ccol + 4];
    }
#pragma unroll
    for (int i = 0; i < 8; i++) {
        float* cp = C + (size_t)(crow + i) * NTOT + ccol;
        float o[8];
#pragma unroll
        for (int j = 0; j < 8; j++) {
            float v = acc[i][j];
            if (EPI) v = lrelu(v + bv[j]);
            o[j] = v;
        }
        *(float4*)&cp[0] = *(float4*)&o[0];
        *(float4*)&cp[4] = *(float4*)&o[4];
    }
}

// ------------------------- correlation kernel --------------------------------
// one block / batch: corr (output, diag=1) + normalized corrn (scratch)
__global__ __launch_bounds__(256) void corr_kernel(const float* __restrict__ h,
                                                   float* __restrict__ corr_out) {
    const int b = blockIdx.x;
    const float* hb = h + (size_t)b * N_NODES * FOUT;
    const int tid = threadIdx.x, lane = tid & 31, warp = tid >> 5;  // 8 warps
    __shared__ float rn[14];
    __shared__ float cmat[196];
    __shared__ float dd[14];

    for (int i = warp; i < 14; i += 8) {
        float s = 0.f;
        for (int c = lane; c < FOUT; c += 32) {
            float v = __ldg(hb + i * FOUT + c);
            s = fmaf(v, v, s);
        }
        s = wred(s);
        if (!lane) rn[i] = rsqrtf(fmaxf(s, 1e-16f));
    }
    __syncthreads();

    for (int p = warp; p < 91; p += 8) {       // 91 pairs i<j
        int i = 0, rem = p;
        while (rem >= 13 - i) { rem -= 13 - i; i++; }
        int j = i + 1 + rem;
        float s = 0.f;
        for (int c = lane; c < FOUT; c += 32)
            s = fmaf(__ldg(hb + i * FOUT + c), __ldg(hb + j * FOUT + c), s);
        s = wred(s);
        if (!lane) {
            float v = fabsf(s * rn[i] * rn[j]);
            cmat[i * 14 + j] = v;
            cmat[j * 14 + i] = v;
        }
    }
    if (tid < 14) cmat[tid * 14 + tid] = 1.f;
    __syncthreads();
    if (tid < 14) {
        float s = 0.f;
        for (int j = 0; j < 14; j++) s += cmat[tid * 14 + j];
        dd[tid] = 1.f / sqrtf(fmaxf(s, 1.f));
    }
    __syncthreads();
    if (tid < 196) {
        int i = tid / 14, j = tid % 14;
        corr_out[(size_t)b * 196 + tid] = cmat[tid];
        g_corrn[(size_t)b * 196 + tid] = dd[i] * cmat[tid] * dd[j];
    }
}

// ------------------------- branch-1 aggregation + BN stats -------------------
__global__ __launch_bounds__(128) void agg1_kernel(const float* __restrict__ b1,
                                                   double* __restrict__ part) {
    const int b = blockIdx.x, tid = threadIdx.x, lane = tid & 31, warp = tid >> 5;
    __shared__ float sh[14 * 512];
    __shared__ float sA1[196], sA2[196];
    __shared__ float red[4][14][4];  // {s1,q1,s3,q3}[node][warp]
    for (int t = tid; t < 196; t += 128) { sA1[t] = g_A1n[t]; sA2[t] = g_A2n[t]; }
    const float4* src = (const float4*)(g_xw1 + (size_t)b * 7168);
    float4* d4 = (float4*)sh;
#pragma unroll
    for (int k = 0; k < 14; k++) d4[tid + k * 128] = src[tid + k * 128];
    __syncthreads();
    float biasv[4];
#pragma unroll
    for (int t = 0; t < 4; t++) biasv[t] = b1[tid + t * 128];
    float* p1 = g_pre1 + (size_t)b * 7168;
    float* p3 = g_pre3 + (size_t)b * 7168;
#pragma unroll 1
    for (int i = 0; i < 14; i++) {
        float w1[14], w2[14];
#pragma unroll
        for (int j = 0; j < 14; j++) { w1[j] = sA1[i * 14 + j]; w2[j] = sA2[i * 14 + j]; }
        float s1 = 0, q1 = 0, s3 = 0, q3 = 0;
#pragma unroll
        for (int t = 0; t < 4; t++) {
            int c = tid + t * 128;
            float a1 = biasv[t], a3 = biasv[t];
#pragma unroll
            for (int j = 0; j < 14; j++) {
                float v = sh[j * 512 + c];
                a1 = fmaf(w1[j], v, a1);
                a3 = fmaf(w2[j], v, a3);
            }
            p1[i * 512 + c] = a1;
            p3[i * 512 + c] = a3;
            s1 += a1; q1 = fmaf(a1, a1, q1);
            s3 += a3; q3 = fmaf(a3, a3, q3);
        }
        s1 = wred(s1); q1 = wred(q1); s3 = wred(s3); q3 = wred(q3);
        if (!lane) { red[0][i][warp] = s1; red[1][i][warp] = q1; red[2][i][warp] = s3; red[3][i][warp] = q3; }
    }
    __syncthreads();
    if (tid < 28) {
        int node = tid % 14, st = tid / 14;
        double v1 = (double)red[st][node][0] + red[st][node][1] + red[st][node][2] + red[st][node][3];
        double v3 = (double)red[st + 2][node][0] + red[st + 2][node][1] + red[st + 2][node][2] + red[st + 2][node][3];
        part[(((size_t)0 * BATCH + b) * 14 + node) * 2 + st] = v1;
        part[(((size_t)1 * BATCH + b) * 14 + node) * 2 + st] = v3;
    }
}

// ------------------------- branch-2 aggregation (stats / write) --------------
template <bool WRITE>
__global__ __launch_bounds__(256) void agg2_kernel(const float* __restrict__ b2,
                                                   double* __restrict__ part,
                                                   float* __restrict__ out) {
    const int b = blockIdx.x, tid = threadIdx.x, lane = tid & 31, warp = tid >> 5;
    __shared__ float sadj[196];
    __shared__ float red[4][14][8];
    if (tid < 196) sadj[tid] = g_corrn[(size_t)b * 196 + tid];
    __syncthreads();
    const float* xa = g_xw2a + (size_t)b * 14336;
    const float* xb = g_xw2b + (size_t)b * 14336;
    float biasv[4];
#pragma unroll
    for (int t = 0; t < 4; t++) biasv[t] = b2[tid + t * 256];
#pragma unroll 1
    for (int i = 0; i < 14; i++) {
        float w[14];
#pragma unroll
        for (int j = 0; j < 14; j++) w[j] = sadj[i * 14 + j];
        float sc2 = 0, sh2 = 0, sc4 = 0, sh4 = 0;
        if (WRITE) {
            sc2 = g_scale[2][i]; sh2 = g_shift[2][i];
            sc4 = g_scale[3][i]; sh4 = g_shift[3][i];
        }
        float s2 = 0, q2 = 0, s4 = 0, q4 = 0;
#pragma unroll
        for (int t = 0; t < 4; t++) {
            int c = tid + t * 256;
            float a2 = biasv[t], a4 = biasv[t];
#pragma unroll
            for (int j = 0; j < 14; j++) {
                a2 = fmaf(w[j], __ldg(xb + j * 1024 + c), a2);
                a4 = fmaf(w[j], __ldg(xa + j * 1024 + c), a4);
            }
            if (WRITE) {
                out[((size_t)b * 14 + i) * 1024 + c] =
                    lrelu(fmaf(a2, sc2, sh2)) + lrelu(fmaf(a4, sc4, sh4));
            } else {
                s2 += a2; q2 = fmaf(a2, a2, q2);
                s4 += a4; q4 = fmaf(a4, a4, q4);
            }
        }
        if (!WRITE) {
            s2 = wred(s2); q2 = wred(q2); s4 = wred(s4); q4 = wred(q4);
            if (!lane) { red[0][i][warp] = s2; red[1][i][warp] = q2; red[2][i][warp] = s4; red[3][i][warp] = q4; }
        }
    }
    if (!WRITE) {
        __syncthreads();
        if (tid < 28) {
            int node = tid % 14, st = tid / 14;
            double v2 = 0, v4 = 0;
#pragma unroll
            for (int wq = 0; wq < 8; wq++) {
                v2 += (double)red[st][node][wq];
                v4 += (double)red[st + 2][node][wq];
            }
            part[(((size_t)2 * BATCH + b) * 14 + node) * 2 + st] = v2;
            part[(((size_t)3 * BATCH + b) * 14 + node) * 2 + st] = v4;
        }
    }
}

// ------------------------- deterministic BN reduce ---------------------------
__global__ __launch_bounds__(1024) void bn_reduce_kernel(
    int setA, int setB, const float* __restrict__ gA, const float* __restrict__ bA,
    const float* __restrict__ gB, const float* __restrict__ bB,
    double invCount, const double* __restrict__ part) {
    __shared__ double chunk[56][32];
    const int tid = threadIdx.x;
    for (int task = tid; task < 1792; task += 1024) {
        int series = task >> 5, ch = task & 31;
        int set = (series < 28) ? setA : setB;
        int rem = series % 28;
        int node = rem >> 1, st = rem & 1;
        double s = 0;
        int b0 = ch * 128;
        for (int bb = 0; bb < 128; bb++)
            s += part[(((size_t)set * BATCH + b0 + bb) * 14 + node) * 2 + st];
        chunk[series][ch] = s;
    }
    __syncthreads();
    if (tid < 28) {
        int setidx = tid / 14, node = tid % 14;
        int set = setidx ? setB : setA;
        double S = 0, Q = 0;
        for (int ch = 0; ch < 32; ch++) {
            S += chunk[setidx * 28 + node * 2 + 0][ch];
            Q += chunk[setidx * 28 + node * 2 + 1][ch];
        }
        double mean = S * invCount;
        double var = Q * invCount - mean * mean;
        const float* g = setidx ? gB : gA;
        const float* be = setidx ? bB : bA;
        double sc = (double)g[node] / sqrt(var + 1e-5);
        g_scale[set][node] = (float)sc;
        g_shift[set][node] = (float)((double)be[node] - mean * sc);
    }
}

// ------------------------- host launcher -------------------------------------
static float* sym_addr(const void* sym) {
    void* p = nullptr;
    cudaGetSymbolAddress(&p, sym);
    return (float*)p;
}

extern "C" void kernel_launch(void* const* d_in, const int* in_sizes, int n_in,
                              void* d_out, int out_size) {
    const float* x     = (const float*)d_in[0];
    const float* adj1  = (const float*)d_in[1];
    const float* adj2  = (const float*)d_in[2];
    const float* fc_w  = (const float*)d_in[3];
    const float* fc_b  = (const float*)d_in[4];
    const float* g1w   = (const float*)d_in[5];
    const float* g1b   = (const float*)d_in[6];
    const float* g2w   = (const float*)d_in[7];
    const float* g2b   = (const float*)d_in[8];
    const float* gamma1 = (const float*)d_in[9];
    const float* beta1  = (const float*)d_in[10];
    const float* gamma2 = (const float*)d_in[11];
    const float* beta2  = (const float*)d_in[12];
    const float* gamma3 = (const float*)d_in[13];
    const float* beta3  = (const float*)d_in[14];

    float* out      = (float*)d_out;
    float* corr_out = out + OFF_CORR;
    float* h_out    = out + OFF_H;

    float*  p_xw1  = sym_addr(g_xw1);
    float*  p_pre1 = sym_addr(g_pre1);
    float*  p_pre3 = sym_addr(g_pre3);
    float*  p_xw2a = sym_addr(g_xw2a);
    float*  p_xw2b = sym_addr(g_xw2b);
    double* p_part = (double*)sym_addr(g_part);

    prep_adj<<<1, 196>>>(adj1, adj2);

    // h = lrelu(x @ fc_w + fc_b)
    sgemm_k<1024, 1024, -1, true><<<dim3(8, 448), 256>>>(x, fc_w, fc_b, h_out);
    corr_kernel<<<BATCH, 256>>>(h_out, corr_out);

    // xw1 = x @ gcn1_w
    sgemm_k<1024, 512, -1, false><<<dim3(4, 448), 256>>>(x, g1w, nullptr, p_xw1);
    agg1_kernel<<<BATCH, 128>>>(g1b, p_part);
    bn_reduce_kernel<<<1, 1024>>>(0, 1, gamma1, beta1, gamma3, beta3,
                                  1.0 / ((double)BATCH * HID), p_part);

    // xw2b = lrelu(bn(pre1)) @ gcn2_w ; xw2a = lrelu(bn(pre3)) @ gcn2_w
    sgemm_k<512, 1024, 0, false><<<dim3(8, 448), 256>>>(p_pre1, g2w, nullptr, p_xw2b);
    sgemm_k<512, 1024, 1, false><<<dim3(8, 448), 256>>>(p_pre3, g2w, nullptr, p_xw2a);

    agg2_kernel<false><<<BATCH, 256>>>(g2b, p_part, nullptr);
    bn_reduce_kernel<<<1, 1024>>>(2, 3, gamma2, beta2, gamma2, beta2,
                                  1.0 / ((double)BATCH * FOUT), p_part);
    agg2_kernel<true><<<BATCH, 256>>>(g2b, p_part, out);

    (void)in_sizes; (void)n_in; (void)out_size;
}

// round 4
// speedup vs baseline: 2.0037x; 2.0037x over previous
#include <cuda_runtime.h>
#include <cuda_bf16.h>
#include <cstddef>
#include <cstdint>

#define N_NODES 14
#define BATCH   4096
#define FIN     1024
#define FOUT    1024
#define HID     512
#define MROWS   (BATCH * N_NODES)        /* 57344 */

#define SZ_FINAL (MROWS * FOUT)
#define SZ_CORR  (BATCH * N_NODES * N_NODES)
#define OFF_CORR SZ_FINAL
#define OFF_H    (OFF_CORR + SZ_CORR)

// ------------------------- device scratch -----------------------------------
__device__ __align__(256) __nv_bfloat16 g_xhi[MROWS * 1024];   // also reused: cvt(pre) stacked [2*MROWS][512]
__device__ __align__(256) __nv_bfloat16 g_xlo[MROWS * 1024];
__device__ __align__(256) __nv_bfloat16 g_wfc_h[1024 * 1024];
__device__ __align__(256) __nv_bfloat16 g_wfc_l[1024 * 1024];
__device__ __align__(256) __nv_bfloat16 g_w1_h[512 * 1024];
__device__ __align__(256) __nv_bfloat16 g_w1_l[512 * 1024];
__device__ __align__(256) __nv_bfloat16 g_w2_h[1024 * 512];
__device__ __align__(256) __nv_bfloat16 g_w2_l[1024 * 512];
__device__ float  g_A1n[196];
__device__ float  g_A2n[196];
__device__ float  g_xw1 [MROWS * HID];
__device__ float  g_pre1[MROWS * HID];
__device__ float  g_pre3[MROWS * HID];
__device__ float  g_xw2[2u * MROWS * FOUT];   // stacked [xw2b ; xw2a]
__device__ float  g_corrn[BATCH * 196];
__device__ double g_part[4 * BATCH * 14 * 2];
__device__ float  g_scale[4][14];
__device__ float  g_shift[4][14];

__device__ __forceinline__ float lrelu(float v) { return v > 0.f ? v : 0.2f * v; }

__device__ __forceinline__ float wred(float v) {
#pragma unroll
    for (int o = 16; o; o >>= 1) v += __shfl_xor_sync(0xffffffffu, v, o);
    return v;
}

// ------------------------- adjacency prep -----------------------------------
__global__ void prep_adj(const float* __restrict__ adj1, const float* __restrict__ adj2) {
    __shared__ float a[2][196];
    __shared__ float dv[2][14];
    int t = threadIdx.x;                 // 196 threads
    int i = t / 14, j = t % 14;
    a[0][t] = (i == j) ? 1.f : adj1[t];
    a[1][t] = (i == j) ? 1.f : adj2[t];
    __syncthreads();
    if (t < 28) {
        int s = t / 14, r = t % 14;
        float acc = 0.f;
        for (int c = 0; c < 14; c++) acc += a[s][r * 14 + c];
        dv[s][r] = 1.f / sqrtf(fmaxf(acc, 1.f));
    }
    __syncthreads();
    g_A1n[t] = dv[0][i] * a[0][t] * dv[0][j];
    g_A2n[t] = dv[1][i] * a[1][t] * dv[1][j];
}

// ------------------------- split / transpose kernels -------------------------
// W[K][Nw] fp32 -> Wt_hi/lo [Nw][K] bf16
__global__ void wsplit_k(const float* __restrict__ W, __nv_bfloat16* __restrict__ th,
                         __nv_bfloat16* __restrict__ tl, int K, int Nw) {
    int idx = blockIdx.x * 256 + threadIdx.x;
    if (idx >= K * Nw) return;
    int n = idx / K, k = idx % K;
    float v = W[(size_t)k * Nw + n];
    __nv_bfloat16 h = __float2bfloat16(v);
    th[idx] = h;
    tl[idx] = __float2bfloat16(v - __bfloat162float(h));
}

__device__ __forceinline__ void split2(float x, float y, __nv_bfloat162& h2, __nv_bfloat162& l2) {
    __nv_bfloat16 hx = __float2bfloat16(x), hy = __float2bfloat16(y);
    h2.x = hx; h2.y = hy;
    l2.x = __float2bfloat16(x - __bfloat162float(hx));
    l2.y = __float2bfloat16(y - __bfloat162float(hy));
}

__global__ void xsplit_k(const float4* __restrict__ src, __nv_bfloat162* __restrict__ hi,
                         __nv_bfloat162* __restrict__ lo, int n4) {
    int i = blockIdx.x * 256 + threadIdx.x;
    if (i >= n4) return;
    float4 v = src[i];
    __nv_bfloat162 h0, l0, h1, l1;
    split2(v.x, v.y, h0, l0);
    split2(v.z, v.w, h1, l1);
    hi[2 * i] = h0; hi[2 * i + 1] = h1;
    lo[2 * i] = l0; lo[2 * i + 1] = l1;
}

// pre (fp32 [MROWS][512]) -> lrelu(bn(.)) -> bf16 hi/lo
__global__ void bnsplit_k(const float4* __restrict__ src, __nv_bfloat162* __restrict__ hi,
                          __nv_bfloat162* __restrict__ lo, int preset, int n4) {
    int i = blockIdx.x * 256 + threadIdx.x;
    if (i >= n4) return;
    int node = (i >> 7) % 14;            // 128 float4 per 512-row
    float sc = g_scale[preset][node], sh = g_shift[preset][node];
    float4 v = src[i];
    v.x = lrelu(fmaf(v.x, sc, sh));
    v.y = lrelu(fmaf(v.y, sc, sh));
    v.z = lrelu(fmaf(v.z, sc, sh));
    v.w = lrelu(fmaf(v.w, sc, sh));
    __nv_bfloat162 h0, l0, h1, l1;
    split2(v.x, v.y, h0, l0);
    split2(v.z, v.w, h1, l1);
    hi[2 * i] = h0; hi[2 * i + 1] = h1;
    lo[2 * i] = l0; lo[2 * i + 1] = l1;
}

// ------------------------- bf16-split tensor-core GEMM -----------------------
__device__ __forceinline__ void cpa16(uint32_t dst, const void* src) {
    asm volatile("cp.async.cg.shared.global [%0], [%1], 16;\n" :: "r"(dst), "l"(src));
}
__device__ __forceinline__ void cpcommit() { asm volatile("cp.async.commit_group;\n"); }
__device__ __forceinline__ void cpwait0()  { asm volatile("cp.async.wait_group 0;\n"); }
__device__ __forceinline__ void ldm_x4(uint32_t& r0, uint32_t& r1, uint32_t& r2, uint32_t& r3, uint32_t a) {
    asm volatile("ldmatrix.sync.aligned.m8n8.x4.shared.b16 {%0,%1,%2,%3},[%4];\n"
                 : "=r"(r0), "=r"(r1), "=r"(r2), "=r"(r3) : "r"(a));
}
__device__ __forceinline__ void mma_bf16(float* c, const uint32_t* a, uint32_t b0, uint32_t b1) {
    asm volatile("mma.sync.aligned.m16n8k16.row.col.f32.bf16.bf16.f32 "
                 "{%0,%1,%2,%3},{%4,%5,%6,%7},{%8,%9},{%0,%1,%2,%3};\n"
                 : "+f"(c[0]), "+f"(c[1]), "+f"(c[2]), "+f"(c[3])
                 : "r"(a[0]), "r"(a[1]), "r"(a[2]), "r"(a[3]), "r"(b0), "r"(b1));
}

#define SPITCH 40                       /* halves; 80B rows, 80/16=5 odd -> conflict-free ldmatrix */
#define TSZB   (128 * SPITCH * 2)       /* 10240 B per matrix per stage */
#define HSMEM  (8 * TSZB)               /* 81920 B dynamic smem */

// C[M x NTOT] = (Ah+Al)[M x KTOT] * (Bh+Bl)^T, B stored [NTOT][KTOT]
template <int KTOT, int NTOT, bool EPI>
__global__ __launch_bounds__(256, 2)
void hgemm_k(const __nv_bfloat16* __restrict__ Ah, const __nv_bfloat16* __restrict__ Al,
             const __nv_bfloat16* __restrict__ Bh, const __nv_bfloat16* __restrict__ Bl,
             const float* __restrict__ bias, float* __restrict__ C) {
    extern __shared__ __nv_bfloat16 dsm[];
    const uint32_t sbase = (uint32_t)__cvta_generic_to_shared(dsm);
    const int tid = threadIdx.x, lane = tid & 31, wid = tid >> 5;
    const int bx = blockIdx.x, by = blockIdx.y;
    const int wm = wid & 3, wn = wid >> 2;

    const int lrow = tid >> 1, lc = (tid & 1) * 2;
    const size_t arow = (size_t)(by * 128 + lrow) * KTOT;
    const size_t brow = (size_t)(bx * 128 + lrow) * KTOT;
    const uint32_t sdrow = (uint32_t)lrow * SPITCH * 2;

    float acc[2][8][4];
#pragma unroll
    for (int i = 0; i < 2; i++)
#pragma unroll
        for (int j = 0; j < 8; j++)
#pragma unroll
            for (int q = 0; q < 4; q++) acc[i][j][q] = 0.f;

    const int NK = KTOT / 32;

#define LOAD_TILE(KT, S) do {                                             \
        uint32_t st_ = sbase + (S) * 4 * TSZB;                            \
        int kh_ = (KT) * 32;                                              \
        _Pragma("unroll")                                                 \
        for (int c_ = 0; c_ < 2; c_++) {                                  \
            int ch_ = lc + c_;                                            \
            uint32_t dof_ = sdrow + ch_ * 16;                             \
            cpa16(st_ + 0 * TSZB + dof_, Ah + arow + kh_ + ch_ * 8);      \
            cpa16(st_ + 1 * TSZB + dof_, Al + arow + kh_ + ch_ * 8);      \
            cpa16(st_ + 2 * TSZB + dof_, Bh + brow + kh_ + ch_ * 8);      \
            cpa16(st_ + 3 * TSZB + dof_, Bl + brow + kh_ + ch_ * 8);      \
        }                                                                 \
    } while (0)

    LOAD_TILE(0, 0);
    cpcommit();

    for (int kt = 0; kt < NK; kt++) {
        cpwait0();
        __syncthreads();
        if (kt + 1 < NK) { LOAD_TILE(kt + 1, (kt + 1) & 1); cpcommit(); }
        const uint32_t st = sbase + (kt & 1) * 4 * TSZB;
#pragma unroll
        for (int khalf = 0; khalf < 32; khalf += 16) {
            uint32_t ah[2][4], al[2][4];
#pragma unroll
            for (int ms = 0; ms < 2; ms++) {
                int row  = wm * 32 + ms * 16 + ((lane >> 3) & 1) * 8 + (lane & 7);
                int kcol = khalf + (lane >> 4) * 8;
                uint32_t off = (uint32_t)(row * SPITCH + kcol) * 2;
                ldm_x4(ah[ms][0], ah[ms][1], ah[ms][2], ah[ms][3], st + 0 * TSZB + off);
                ldm_x4(al[ms][0], al[ms][1], al[ms][2], al[ms][3], st + 1 * TSZB + off);
            }
#pragma unroll
            for (int np = 0; np < 4; np++) {
                int nrow = wn * 64 + np * 16 + (lane >> 4) * 8 + (lane & 7);
                int kcol = khalf + ((lane >> 3) & 1) * 8;
                uint32_t off = (uint32_t)(nrow * SPITCH + kcol) * 2;
                uint32_t bh[4], bl[4];
                ldm_x4(bh[0], bh[1], bh[2], bh[3], st + 2 * TSZB + off);
                ldm_x4(bl[0], bl[1], bl[2], bl[3], st + 3 * TSZB + off);
#pragma unroll
                for (int ms = 0; ms < 2; ms++)
#pragma unroll
                    for (int q = 0; q < 2; q++) {
                        float* cacc = acc[ms][np * 2 + q];
                        mma_bf16(cacc, ah[ms], bh[2 * q], bh[2 * q + 1]);
                        mma_bf16(cacc, ah[ms], bl[2 * q], bl[2 * q + 1]);
                        mma_bf16(cacc, al[ms], bh[2 * q], bh[2 * q + 1]);
                    }
            }
        }
    }

    // epilogue
    const int rbase = by * 128 + wm * 32;
    const int cbase = bx * 128 + wn * 64;
    const int rq = lane >> 2, cq = (lane & 3) * 2;
#pragma unroll
    for (int ms = 0; ms < 2; ms++)
#pragma unroll
        for (int ns = 0; ns < 8; ns++) {
            int r0  = rbase + ms * 16 + rq;
            int col = cbase + ns * 8 + cq;
            float v0 = acc[ms][ns][0], v1 = acc[ms][ns][1];
            float v2 = acc[ms][ns][2], v3 = acc[ms][ns][3];
            if (EPI) {
                float b0 = bias[col], b1 = bias[col + 1];
                v0 = lrelu(v0 + b0); v1 = lrelu(v1 + b1);
                v2 = lrelu(v2 + b0); v3 = lrelu(v3 + b1);
            }
            *(float2*)&C[(size_t)r0 * NTOT + col]       = make_float2(v0, v1);
            *(float2*)&C[(size_t)(r0 + 8) * NTOT + col] = make_float2(v2, v3);
        }
#undef LOAD_TILE
}

// ------------------------- correlation kernel --------------------------------
__global__ __launch_bounds__(256) void corr_kernel(const float* __restrict__ h,
                                                   float* __restrict__ corr_out) {
    const int b = blockIdx.x;
    const float* hb = h + (size_t)b * N_NODES * FOUT;
    const int tid = threadIdx.x, lane = tid & 31, warp = tid >> 5;
    __shared__ float rn[14];
    __shared__ float cmat[196];
    __shared__ float dd[14];

    for (int i = warp; i < 14; i += 8) {
        float s = 0.f;
        for (int c = lane; c < FOUT; c += 32) {
            float v = __ldg(hb + i * FOUT + c);
            s = fmaf(v, v, s);
        }
        s = wred(s);
        if (!lane) rn[i] = rsqrtf(fmaxf(s, 1e-16f));
    }
    __syncthreads();

    for (int p = warp; p < 91; p += 8) {
        int i = 0, rem = p;
        while (rem >= 13 - i) { rem -= 13 - i; i++; }
        int j = i + 1 + rem;
        float s = 0.f;
        for (int c = lane; c < FOUT; c += 32)
            s = fmaf(__ldg(hb + i * FOUT + c), __ldg(hb + j * FOUT + c), s);
        s = wred(s);
        if (!lane) {
            float v = fabsf(s * rn[i] * rn[j]);
            cmat[i * 14 + j] = v;
            cmat[j * 14 + i] = v;
        }
    }
    if (tid < 14) cmat[tid * 14 + tid] = 1.f;
    __syncthreads();
    if (tid < 14) {
        float s = 0.f;
        for (int j = 0; j < 14; j++) s += cmat[tid * 14 + j];
        dd[tid] = 1.f / sqrtf(fmaxf(s, 1.f));
    }
    __syncthreads();
    if (tid < 196) {
        int i = tid / 14, j = tid % 14;
        corr_out[(size_t)b * 196 + tid] = cmat[tid];
        g_corrn[(size_t)b * 196 + tid] = dd[i] * cmat[tid] * dd[j];
    }
}

// ------------------------- branch-1 aggregation + BN stats -------------------
__global__ __launch_bounds__(128) void agg1_kernel(const float* __restrict__ b1,
                                                   double* __restrict__ part) {
    const int b = blockIdx.x, tid = threadIdx.x, lane = tid & 31, warp = tid >> 5;
    __shared__ float sh[14 * 512];
    __shared__ float sA1[196], sA2[196];
    __shared__ float red[4][14][4];
    for (int t = tid; t < 196; t += 128) { sA1[t] = g_A1n[t]; sA2[t] = g_A2n[t]; }
    const float4* src = (const float4*)(g_xw1 + (size_t)b * 7168);
    float4* d4 = (float4*)sh;
#pragma unroll
    for (int k = 0; k < 14; k++) d4[tid + k * 128] = src[tid + k * 128];
    __syncthreads();
    float biasv[4];
#pragma unroll
    for (int t = 0; t < 4; t++) biasv[t] = b1[tid + t * 128];
    float* p1 = g_pre1 + (size_t)b * 7168;
    float* p3 = g_pre3 + (size_t)b * 7168;
#pragma unroll 1
    for (int i = 0; i < 14; i++) {
        float w1[14], w2[14];
#pragma unroll
        for (int j = 0; j < 14; j++) { w1[j] = sA1[i * 14 + j]; w2[j] = sA2[i * 14 + j]; }
        float s1 = 0, q1 = 0, s3 = 0, q3 = 0;
#pragma unroll
        for (int t = 0; t < 4; t++) {
            int c = tid + t * 128;
            float a1 = biasv[t], a3 = biasv[t];
#pragma unroll
            for (int j = 0; j < 14; j++) {
                float v = sh[j * 512 + c];
                a1 = fmaf(w1[j], v, a1);
                a3 = fmaf(w2[j], v, a3);
            }
            p1[i * 512 + c] = a1;
            p3[i * 512 + c] = a3;
            s1 += a1; q1 = fmaf(a1, a1, q1);
            s3 += a3; q3 = fmaf(a3, a3, q3);
        }
        s1 = wred(s1); q1 = wred(q1); s3 = wred(s3); q3 = wred(q3);
        if (!lane) { red[0][i][warp] = s1; red[1][i][warp] = q1; red[2][i][warp] = s3; red[3][i][warp] = q3; }
    }
    __syncthreads();
    if (tid < 28) {
        int node = tid % 14, st = tid / 14;
        double v1 = (double)red[st][node][0] + red[st][node][1] + red[st][node][2] + red[st][node][3];
        double v3 = (double)red[st + 2][node][0] + red[st + 2][node][1] + red[st + 2][node][2] + red[st + 2][node][3];
        part[(((size_t)0 * BATCH + b) * 14 + node) * 2 + st] = v1;
        part[(((size_t)1 * BATCH + b) * 14 + node) * 2 + st] = v3;
    }
}

// ------------------------- branch-2 aggregation (stats / write) --------------
template <bool WRITE>
__global__ __launch_bounds__(256) void agg2_kernel(const float* __restrict__ b2,
                                                   double* __restrict__ part,
                                                   float* __restrict__ out) {
    const int b = blockIdx.x, tid = threadIdx.x, lane = tid & 31, warp = tid >> 5;
    __shared__ float sadj[196];
    __shared__ float red[4][14][8];
    if (tid < 196) sadj[tid] = g_corrn[(size_t)b * 196 + tid];
    __syncthreads();
    const float* xb = g_xw2 + (size_t)b * 14336;                         // from pre1 branch
    const float* xa = g_xw2 + (size_t)MROWS * 1024 + (size_t)b * 14336;  // from pre3 branch
    float biasv[4];
#pragma unroll
    for (int t = 0; t < 4; t++) biasv[t] = b2[tid + t * 256];
#pragma unroll 1
    for (int i = 0; i < 14; i++) {
        float w[14];
#pragma unroll
        for (int j = 0; j < 14; j++) w[j] = sadj[i * 14 + j];
        float sc2 = 0, sh2 = 0, sc4 = 0, sh4 = 0;
        if (WRITE) {
            sc2 = g_scale[2][i]; sh2 = g_shift[2][i];
            sc4 = g_scale[3][i]; sh4 = g_shift[3][i];
        }
        float s2 = 0, q2 = 0, s4 = 0, q4 = 0;
#pragma unroll
        for (int t = 0; t < 4; t++) {
            int c = tid + t * 256;
            float a2 = biasv[t], a4 = biasv[t];
#pragma unroll
            for (int j = 0; j < 14; j++) {
                a2 = fmaf(w[j], __ldg(xb + j * 1024 + c), a2);
                a4 = fmaf(w[j], __ldg(xa + j * 1024 + c), a4);
            }
            if (WRITE) {
                out[((size_t)b * 14 + i) * 1024 + c] =
                    lrelu(fmaf(a2, sc2, sh2)) + lrelu(fmaf(a4, sc4, sh4));
            } else {
                s2 += a2; q2 = fmaf(a2, a2, q2);
                s4 += a4; q4 = fmaf(a4, a4, q4);
            }
        }
        if (!WRITE) {
            s2 = wred(s2); q2 = wred(q2); s4 = wred(s4); q4 = wred(q4);
            if (!lane) { red[0][i][warp] = s2; red[1][i][warp] = q2; red[2][i][warp] = s4; red[3][i][warp] = q4; }
        }
    }
    if (!WRITE) {
        __syncthreads();
        if (tid < 28) {
            int node = tid % 14, st = tid / 14;
            double v2 = 0, v4 = 0;
#pragma unroll
            for (int wq = 0; wq < 8; wq++) {
                v2 += (double)red[st][node][wq];
                v4 += (double)red[st + 2][node][wq];
            }
            part[(((size_t)2 * BATCH + b) * 14 + node) * 2 + st] = v2;
            part[(((size_t)3 * BATCH + b) * 14 + node) * 2 + st] = v4;
        }
    }
}

// ------------------------- deterministic BN reduce ---------------------------
__global__ __launch_bounds__(1024) void bn_reduce_kernel(
    int setA, int setB, const float* __restrict__ gA, const float* __restrict__ bA,
    const float* __restrict__ gB, const float* __restrict__ bB,
    double invCount, const double* __restrict__ part) {
    __shared__ double chunk[56][32];
    const int tid = threadIdx.x;
    for (int task = tid; task < 1792; task += 1024) {
        int series = task >> 5, ch = task & 31;
        int set = (series < 28) ? setA : setB;
        int rem = series % 28;
        int node = rem >> 1, st = rem & 1;
        double s = 0;
        int b0 = ch * 128;
        for (int bb = 0; bb < 128; bb++)
            s += part[(((size_t)set * BATCH + b0 + bb) * 14 + node) * 2 + st];
        chunk[series][ch] = s;
    }
    __syncthreads();
    if (tid < 28) {
        int setidx = tid / 14, node = tid % 14;
        int set = setidx ? setB : setA;
        double S = 0, Q = 0;
        for (int ch = 0; ch < 32; ch++) {
            S += chunk[setidx * 28 + node * 2 + 0][ch];
            Q += chunk[setidx * 28 + node * 2 + 1][ch];
        }
        double mean = S * invCount;
        double var = Q * invCount - mean * mean;
        const float* g = setidx ? gB : gA;
        const float* be = setidx ? bB : bA;
        double sc = (double)g[node] / sqrt(var + 1e-5);
        g_scale[set][node] = (float)sc;
        g_shift[set][node] = (float)((double)be[node] - mean * sc);
    }
}

// ------------------------- host launcher -------------------------------------
static void* sym_addr(const void* sym) {
    void* p = nullptr;
    cudaGetSymbolAddress(&p, sym);
    return p;
}

extern "C" void kernel_launch(void* const* d_in, const int* in_sizes, int n_in,
                              void* d_out, int out_size) {
    const float* x     = (const float*)d_in[0];
    const float* adj1  = (const float*)d_in[1];
    const float* adj2  = (const float*)d_in[2];
    const float* fc_w  = (const float*)d_in[3];
    const float* fc_b  = (const float*)d_in[4];
    const float* g1w   = (const float*)d_in[5];
    const float* g1b   = (const float*)d_in[6];
    const float* g2w   = (const float*)d_in[7];
    const float* g2b   = (const float*)d_in[8];
    const float* gamma1 = (const float*)d_in[9];
    const float* beta1  = (const float*)d_in[10];
    const float* gamma2 = (const float*)d_in[11];
    const float* beta2  = (const float*)d_in[12];
    const float* gamma3 = (const float*)d_in[13];
    const float* beta3  = (const float*)d_in[14];

    float* out      = (float*)d_out;
    float* corr_out = out + OFF_CORR;
    float* h_out    = out + OFF_H;

    __nv_bfloat16* p_xhi  = (__nv_bfloat16*)sym_addr(g_xhi);
    __nv_bfloat16* p_xlo  = (__nv_bfloat16*)sym_addr(g_xlo);
    __nv_bfloat16* p_wfch = (__nv_bfloat16*)sym_addr(g_wfc_h);
    __nv_bfloat16* p_wfcl = (__nv_bfloat16*)sym_addr(g_wfc_l);
    __nv_bfloat16* p_w1h  = (__nv_bfloat16*)sym_addr(g_w1_h);
    __nv_bfloat16* p_w1l  = (__nv_bfloat16*)sym_addr(g_w1_l);
    __nv_bfloat16* p_w2h  = (__nv_bfloat16*)sym_addr(g_w2_h);
    __nv_bfloat16* p_w2l  = (__nv_bfloat16*)sym_addr(g_w2_l);
    float*  p_xw1  = (float*)sym_addr(g_xw1);
    float*  p_pre1 = (float*)sym_addr(g_pre1);
    float*  p_pre3 = (float*)sym_addr(g_pre3);
    float*  p_xw2  = (float*)sym_addr(g_xw2);
    double* p_part = (double*)sym_addr(g_part);

    cudaFuncSetAttribute(hgemm_k<1024, 1024, true >, cudaFuncAttributeMaxDynamicSharedMemorySize, HSMEM);
    cudaFuncSetAttribute(hgemm_k<1024,  512, false>, cudaFuncAttributeMaxDynamicSharedMemorySize, HSMEM);
    cudaFuncSetAttribute(hgemm_k< 512, 1024, false>, cudaFuncAttributeMaxDynamicSharedMemorySize, HSMEM);

    prep_adj<<<1, 196>>>(adj1, adj2);

    // weight transpose + split (tiny)
    wsplit_k<<<(1024 * 1024 + 255) / 256, 256>>>(fc_w, p_wfch, p_wfcl, 1024, 1024);
    wsplit_k<<<(512 * 1024 + 255) / 256, 256>>>(g1w, p_w1h, p_w1l, 1024, 512);
    wsplit_k<<<(1024 * 512 + 255) / 256, 256>>>(g2w, p_w2h, p_w2l, 512, 1024);

    // split x -> bf16 hi/lo
    {
        int n4 = MROWS * 1024 / 4;
        xsplit_k<<<(n4 + 255) / 256, 256>>>((const float4*)x,
                                            (__nv_bfloat162*)p_xhi, (__nv_bfloat162*)p_xlo, n4);
    }

    // h = lrelu(x @ fc_w + fc_b)
    hgemm_k<1024, 1024, true><<<dim3(8, 448), 256, HSMEM>>>(p_xhi, p_xlo, p_wfch, p_wfcl, fc_b, h_out);
    corr_kernel<<<BATCH, 256>>>(h_out, corr_out);

    // xw1 = x @ gcn1_w
    hgemm_k<1024, 512, false><<<dim3(4, 448), 256, HSMEM>>>(p_xhi, p_xlo, p_w1h, p_w1l, nullptr, p_xw1);
    agg1_kernel<<<BATCH, 128>>>(g1b, p_part);
    bn_reduce_kernel<<<1, 1024>>>(0, 1, gamma1, beta1, gamma3, beta3,
                                  1.0 / ((double)BATCH * HID), p_part);

    // convert lrelu(bn(pre1)), lrelu(bn(pre3)) -> stacked bf16 hi/lo (reuses x buffers)
    {
        int n4 = MROWS * 512 / 4;
        bnsplit_k<<<(n4 + 255) / 256, 256>>>((const float4*)p_pre1,
                                             (__nv_bfloat162*)p_xhi, (__nv_bfloat162*)p_xlo, 0, n4);
        bnsplit_k<<<(n4 + 255) / 256, 256>>>((const float4*)p_pre3,
                                             (__nv_bfloat162*)(p_xhi + (size_t)MROWS * 512),
                                             (__nv_bfloat162*)(p_xlo + (size_t)MROWS * 512), 1, n4);
    }

    // stacked GEMM: [cvt(pre1); cvt(pre3)] @ gcn2_w  -> g_xw2 (2*MROWS x 1024)
    hgemm_k<512, 1024, false><<<dim3(8, 896), 256, HSMEM>>>(p_xhi, p_xlo, p_w2h, p_w2l, nullptr, p_xw2);

    agg2_kernel<false><<<BATCH, 256>>>(g2b, p_part, nullptr);
    bn_reduce_kernel<<<1, 1024>>>(2, 3, gamma2, beta2, gamma2, beta2,
                                  1.0 / ((double)BATCH * FOUT), p_part);
    agg2_kernel<true><<<BATCH, 256>>>(g2b, p_part, out);

    (void)in_sizes; (void)n_in; (void)out_size;
}

// round 6
// speedup vs baseline: 2.0252x; 1.0107x over previous
#include <cuda_runtime.h>
#include <cuda_bf16.h>
#include <cstddef>
#include <cstdint>

#define N_NODES 14
#define BATCH   4096
#define FIN     1024
#define FOUT    1024
#define HID     512
#define MROWS   (BATCH * N_NODES)        /* 57344 */

#define SZ_FINAL (MROWS * FOUT)
#define SZ_CORR  (BATCH * N_NODES * N_NODES)
#define OFF_CORR SZ_FINAL
#define OFF_H    (OFF_CORR + SZ_CORR)

// ------------------------- device scratch -----------------------------------
__device__ __align__(256) __nv_bfloat16 g_xhi[MROWS * 1024];   // reused: cvt(pre) stacked [2*MROWS][512]
__device__ __align__(256) __nv_bfloat16 g_xlo[MROWS * 1024];
__device__ __align__(256) __nv_bfloat16 g_wfc_h[1024 * 1024];
__device__ __align__(256) __nv_bfloat16 g_wfc_l[1024 * 1024];
__device__ __align__(256) __nv_bfloat16 g_w1_h[512 * 1024];
__device__ __align__(256) __nv_bfloat16 g_w1_l[512 * 1024];
__device__ __align__(256) __nv_bfloat16 g_w2_h[1024 * 512];
__device__ __align__(256) __nv_bfloat16 g_w2_l[1024 * 512];
__device__ float  g_A1n[196];
__device__ float  g_A2n[196];
__device__ float  g_xw1 [MROWS * HID];
__device__ float  g_pre1[MROWS * HID];
__device__ float  g_pre3[MROWS * HID];
__device__ float  g_xw2[2u * MROWS * FOUT];   // stacked [xw2b ; xw2a]
__device__ float  g_corrn[BATCH * 196];
__device__ double g_part[4 * BATCH * 14 * 2];
__device__ float  g_scale[4][14];
__device__ float  g_shift[4][14];

__device__ __forceinline__ float lrelu(float v) { return v > 0.f ? v : 0.2f * v; }

__device__ __forceinline__ float wred(float v) {
#pragma unroll
    for (int o = 16; o; o >>= 1) v += __shfl_xor_sync(0xffffffffu, v, o);
    return v;
}

// ------------------------- adjacency prep -----------------------------------
__global__ void prep_adj(const float* __restrict__ adj1, const float* __restrict__ adj2) {
    __shared__ float a[2][196];
    __shared__ float dv[2][14];
    int t = threadIdx.x;                 // 196 threads
    int i = t / 14, j = t % 14;
    a[0][t] = (i == j) ? 1.f : adj1[t];
    a[1][t] = (i == j) ? 1.f : adj2[t];
    __syncthreads();
    if (t < 28) {
        int s = t / 14, r = t % 14;
        float acc = 0.f;
        for (int c = 0; c < 14; c++) acc += a[s][r * 14 + c];
        dv[s][r] = 1.f / sqrtf(fmaxf(acc, 1.f));
    }
    __syncthreads();
    g_A1n[t] = dv[0][i] * a[0][t] * dv[0][j];
    g_A2n[t] = dv[1][i] * a[1][t] * dv[1][j];
}

// ------------------------- split / transpose kernels -------------------------
__global__ void wsplit_k(const float* __restrict__ W, __nv_bfloat16* __restrict__ th,
                         __nv_bfloat16* __restrict__ tl, int K, int Nw) {
    int idx = blockIdx.x * 256 + threadIdx.x;
    if (idx >= K * Nw) return;
    int n = idx / K, k = idx % K;
    float v = W[(size_t)k * Nw + n];
    __nv_bfloat16 h = __float2bfloat16(v);
    th[idx] = h;
    tl[idx] = __float2bfloat16(v - __bfloat162float(h));
}

__device__ __forceinline__ void split2(float x, float y, __nv_bfloat162& h2, __nv_bfloat162& l2) {
    __nv_bfloat16 hx = __float2bfloat16(x), hy = __float2bfloat16(y);
    h2.x = hx; h2.y = hy;
    l2.x = __float2bfloat16(x - __bfloat162float(hx));
    l2.y = __float2bfloat16(y - __bfloat162float(hy));
}

__global__ void xsplit_k(const float4* __restrict__ src, __nv_bfloat162* __restrict__ hi,
                         __nv_bfloat162* __restrict__ lo, int n4) {
    int i = blockIdx.x * 256 + threadIdx.x;
    if (i >= n4) return;
    float4 v = src[i];
    __nv_bfloat162 h0, l0, h1, l1;
    split2(v.x, v.y, h0, l0);
    split2(v.z, v.w, h1, l1);
    hi[2 * i] = h0; hi[2 * i + 1] = h1;
    lo[2 * i] = l0; lo[2 * i + 1] = l1;
}

__global__ void bnsplit_k(const float4* __restrict__ src, __nv_bfloat162* __restrict__ hi,
                          __nv_bfloat162* __restrict__ lo, int preset, int n4) {
    int i = blockIdx.x * 256 + threadIdx.x;
    if (i >= n4) return;
    int node = (i >> 7) % 14;            // 128 float4 per 512-row
    float sc = g_scale[preset][node], sh = g_shift[preset][node];
    float4 v = src[i];
    v.x = lrelu(fmaf(v.x, sc, sh));
    v.y = lrelu(fmaf(v.y, sc, sh));
    v.z = lrelu(fmaf(v.z, sc, sh));
    v.w = lrelu(fmaf(v.w, sc, sh));
    __nv_bfloat162 h0, l0, h1, l1;
    split2(v.x, v.y, h0, l0);
    split2(v.z, v.w, h1, l1);
    hi[2 * i] = h0; hi[2 * i + 1] = h1;
    lo[2 * i] = l0; lo[2 * i + 1] = l1;
}

// ------------------------- bf16-split tensor-core GEMM -----------------------
__device__ __forceinline__ void cpa16(uint32_t dst, const void* src) {
    asm volatile("cp.async.cg.shared.global [%0], [%1], 16;\n" :: "r"(dst), "l"(src));
}
__device__ __forceinline__ void cpcommit() { asm volatile("cp.async.commit_group;\n"); }
__device__ __forceinline__ void ldm_x4(uint32_t& r0, uint32_t& r1, uint32_t& r2, uint32_t& r3, uint32_t a) {
    asm volatile("ldmatrix.sync.aligned.m8n8.x4.shared.b16 {%0,%1,%2,%3},[%4];\n"
                 : "=r"(r0), "=r"(r1), "=r"(r2), "=r"(r3) : "r"(a));
}
__device__ __forceinline__ void mma_bf16(float* c, const uint32_t* a, uint32_t b0, uint32_t b1) {
    asm volatile("mma.sync.aligned.m16n8k16.row.col.f32.bf16.bf16.f32 "
                 "{%0,%1,%2,%3},{%4,%5,%6,%7},{%8,%9},{%0,%1,%2,%3};\n"
                 : "+f"(c[0]), "+f"(c[1]), "+f"(c[2]), "+f"(c[3])
                 : "r"(a[0]), "r"(a[1]), "r"(a[2]), "r"(a[3]), "r"(b0), "r"(b1));
}

#define SPITCH 40                       /* halves: 80B rows, odd 16B stride -> conflict-free */
#define A_SZ   (128 * SPITCH * 2)       /* 10240 B */
#define B_SZ   (256 * SPITCH * 2)       /* 20480 B */
#define STG    (2 * A_SZ + 2 * B_SZ)    /* 61440 B per stage */
#define HSMEM  (2 * STG)                /* 122880 B */

// C[M x NTOT] = (Ah+Al)[M x KTOT] * (Bh+Bl)^T, B stored [NTOT][KTOT].
// Tile 128 x 256, 256 threads, warp tile 32 x 128.
template <int KTOT, int NTOT, bool EPI>
__global__ __launch_bounds__(256, 1)
void hgemm_k(const __nv_bfloat16* __restrict__ Ah, const __nv_bfloat16* __restrict__ Al,
             const __nv_bfloat16* __restrict__ Bh, const __nv_bfloat16* __restrict__ Bl,
             const float* __restrict__ bias, float* __restrict__ C) {
    extern __shared__ __nv_bfloat16 dsm[];
    const uint32_t sbase = (uint32_t)__cvta_generic_to_shared(dsm);
    const int tid = threadIdx.x, lane = tid & 31, wid = tid >> 5;
    const int bx = blockIdx.x, by = blockIdx.y;
    const int wm = wid & 3, wn = wid >> 2;

    float acc[2][16][4];
#pragma unroll
    for (int i = 0; i < 2; i++)
#pragma unroll
        for (int j = 0; j < 16; j++)
#pragma unroll
            for (int q = 0; q < 4; q++) acc[i][j][q] = 0.f;

    const int NK = KTOT / 32;

#define FILL(KT, S) do {                                                      \
        const uint32_t sb_ = sbase + (S) * STG;                               \
        const int k0_ = (KT) * 32;                                            \
        _Pragma("unroll")                                                     \
        for (int q_ = 0; q_ < 12; q_++) {                                     \
            int idx = tid + q_ * 256;                                         \
            if (idx < 1024) {                                                 \
                int m = idx >> 9, r = (idx >> 2) & 127, c = idx & 3;          \
                const __nv_bfloat16* s_ = (m ? Al : Ah) +                     \
                    (size_t)(by * 128 + r) * KTOT + k0_ + c * 8;              \
                cpa16(sb_ + m * A_SZ + r * 80u + c * 16u, s_);                \
            } else {                                                          \
                int ib = idx - 1024;                                          \
                int m = ib >> 10, r = (ib >> 2) & 255, c = ib & 3;            \
                const __nv_bfloat16* s_ = (m ? Bl : Bh) +                     \
                    (size_t)(bx * 256 + r) * KTOT + k0_ + c * 8;              \
                cpa16(sb_ + 2 * A_SZ + m * B_SZ + r * 80u + c * 16u, s_);     \
            }                                                                 \
        }                                                                     \
        cpcommit();                                                           \
    } while (0)

    FILL(0, 0);

    for (int kt = 0; kt < NK; kt++) {
        if (kt + 1 < NK) {
            FILL(kt + 1, (kt + 1) & 1);
            asm volatile("cp.async.wait_group 1;\n");
        } else {
            asm volatile("cp.async.wait_group 0;\n");
        }
        __syncthreads();

        const uint32_t st = sbase + (kt & 1) * STG;
        const uint32_t stA = st, stB = st + 2 * A_SZ;
#pragma unroll
        for (int khalf = 0; khalf < 32; khalf += 16) {
            uint32_t ah[2][4], al[2][4];
#pragma unroll
            for (int ms = 0; ms < 2; ms++) {
                int row  = wm * 32 + ms * 16 + ((lane >> 3) & 1) * 8 + (lane & 7);
                int kcol = khalf + (lane >> 4) * 8;
                uint32_t off = (uint32_t)(row * SPITCH + kcol) * 2;
                ldm_x4(ah[ms][0], ah[ms][1], ah[ms][2], ah[ms][3], stA + off);
                ldm_x4(al[ms][0], al[ms][1], al[ms][2], al[ms][3], stA + A_SZ + off);
            }
#pragma unroll
            for (int np = 0; np < 8; np++) {
                int nrow = wn * 128 + np * 16 + (lane >> 4) * 8 + (lane & 7);
                int kcol = khalf + ((lane >> 3) & 1) * 8;
                uint32_t off = (uint32_t)(nrow * SPITCH + kcol) * 2;
                uint32_t bh[4], bl[4];
                ldm_x4(bh[0], bh[1], bh[2], bh[3], stB + off);
                ldm_x4(bl[0], bl[1], bl[2], bl[3], stB + B_SZ + off);
#pragma unroll
                for (int ms = 0; ms < 2; ms++)
#pragma unroll
                    for (int q = 0; q < 2; q++) {
                        float* cacc = acc[ms][np * 2 + q];
                        mma_bf16(cacc, ah[ms], bh[2 * q], bh[2 * q + 1]);
                        mma_bf16(cacc, ah[ms], bl[2 * q], bl[2 * q + 1]);
                        mma_bf16(cacc, al[ms], bh[2 * q], bh[2 * q + 1]);
                    }
            }
        }
        __syncthreads();
    }
#undef FILL

    // epilogue
    const int rbase = by * 128 + wm * 32;
    const int cbase = bx * 256 + wn * 128;
    const int rq = lane >> 2, cq = (lane & 3) * 2;
#pragma unroll
    for (int ms = 0; ms < 2; ms++)
#pragma unroll
        for (int ns = 0; ns < 16; ns++) {
            int r0  = rbase + ms * 16 + rq;
            int col = cbase + ns * 8 + cq;
            float v0 = acc[ms][ns][0], v1 = acc[ms][ns][1];
            float v2 = acc[ms][ns][2], v3 = acc[ms][ns][3];
            if (EPI) {
                float b0 = bias[col], b1 = bias[col + 1];
                v0 = lrelu(v0 + b0); v1 = lrelu(v1 + b1);
                v2 = lrelu(v2 + b0); v3 = lrelu(v3 + b1);
            }
            *(float2*)&C[(size_t)r0 * NTOT + col]       = make_float2(v0, v1);
            *(float2*)&C[(size_t)(r0 + 8) * NTOT + col] = make_float2(v2, v3);
        }
}

// ------------------------- correlation kernel --------------------------------
__global__ __launch_bounds__(256) void corr_kernel(const float* __restrict__ h,
                                                   float* __restrict__ corr_out) {
    const int b = blockIdx.x;
    const float* hb = h + (size_t)b * N_NODES * FOUT;
    const int tid = threadIdx.x, lane = tid & 31, warp = tid >> 5;
    __shared__ float rn[14];
    __shared__ float cmat[196];
    __shared__ float dd[14];

    for (int i = warp; i < 14; i += 8) {
        float s = 0.f;
        for (int c = lane; c < FOUT; c += 32) {
            float v = __ldg(hb + i * FOUT + c);
            s = fmaf(v, v, s);
        }
        s = wred(s);
        if (!lane) rn[i] = rsqrtf(fmaxf(s, 1e-16f));
    }
    __syncthreads();

    for (int p = warp; p < 91; p += 8) {
        int i = 0, rem = p;
        while (rem >= 13 - i) { rem -= 13 - i; i++; }
        int j = i + 1 + rem;
        float s = 0.f;
        for (int c = lane; c < FOUT; c += 32)
            s = fmaf(__ldg(hb + i * FOUT + c), __ldg(hb + j * FOUT + c), s);
        s = wred(s);
        if (!lane) {
            float v = fabsf(s * rn[i] * rn[j]);
            cmat[i * 14 + j] = v;
            cmat[j * 14 + i] = v;
        }
    }
    if (tid < 14) cmat[tid * 14 + tid] = 1.f;
    __syncthreads();
    if (tid < 14) {
        float s = 0.f;
        for (int j = 0; j < 14; j++) s += cmat[tid * 14 + j];
        dd[tid] = 1.f / sqrtf(fmaxf(s, 1.f));
    }
    __syncthreads();
    if (tid < 196) {
        int i = tid / 14, j = tid % 14;
        corr_out[(size_t)b * 196 + tid] = cmat[tid];
        g_corrn[(size_t)b * 196 + tid] = dd[i] * cmat[tid] * dd[j];
    }
}

// ------------------------- branch-1 aggregation + BN stats -------------------
__global__ __launch_bounds__(128) void agg1_kernel(const float* __restrict__ b1,
                                                   double* __restrict__ part) {
    const int b = blockIdx.x, tid = threadIdx.x, lane = tid & 31, warp = tid >> 5;
    __shared__ float sh[14 * 512];
    __shared__ float sA1[196], sA2[196];
    __shared__ float red[4][14][4];
    for (int t = tid; t < 196; t += 128) { sA1[t] = g_A1n[t]; sA2[t] = g_A2n[t]; }
    const float4* src = (const float4*)(g_xw1 + (size_t)b * 7168);
    float4* d4 = (float4*)sh;
#pragma unroll
    for (int k = 0; k < 14; k++) d4[tid + k * 128] = src[tid + k * 128];
    __syncthreads();
    float biasv[4];
#pragma unroll
    for (int t = 0; t < 4; t++) biasv[t] = b1[tid + t * 128];
    float* p1 = g_pre1 + (size_t)b * 7168;
    float* p3 = g_pre3 + (size_t)b * 7168;
#pragma unroll 1
    for (int i = 0; i < 14; i++) {
        float w1[14], w2[14];
#pragma unroll
        for (int j = 0; j < 14; j++) { w1[j] = sA1[i * 14 + j]; w2[j] = sA2[i * 14 + j]; }
        float s1 = 0, q1 = 0, s3 = 0, q3 = 0;
#pragma unroll
        for (int t = 0; t < 4; t++) {
            int c = tid + t * 128;
            float a1 = biasv[t], a3 = biasv[t];
#pragma unroll
            for (int j = 0; j < 14; j++) {
                float v = sh[j * 512 + c];
                a1 = fmaf(w1[j], v, a1);
                a3 = fmaf(w2[j], v, a3);
            }
            p1[i * 512 + c] = a1;
            p3[i * 512 + c] = a3;
            s1 += a1; q1 = fmaf(a1, a1, q1);
            s3 += a3; q3 = fmaf(a3, a3, q3);
        }
        s1 = wred(s1); q1 = wred(q1); s3 = wred(s3); q3 = wred(q3);
        if (!lane) { red[0][i][warp] = s1; red[1][i][warp] = q1; red[2][i][warp] = s3; red[3][i][warp] = q3; }
    }
    __syncthreads();
    if (tid < 28) {
        int node = tid % 14, st = tid / 14;
        double v1 = (double)red[st][node][0] + red[st][node][1] + red[st][node][2] + red[st][node][3];
        double v3 = (double)red[st + 2][node][0] + red[st + 2][node][1] + red[st + 2][node][2] + red[st + 2][node][3];
        part[(((size_t)0 * BATCH + b) * 14 + node) * 2 + st] = v1;
        part[(((size_t)1 * BATCH + b) * 14 + node) * 2 + st] = v3;
    }
}

// ------------------------- branch-2 aggregation (stats / write) --------------
template <bool WRITE>
__global__ __launch_bounds__(256) void agg2_kernel(const float* __restrict__ b2,
                                                   double* __restrict__ part,
                                                   float* __restrict__ out) {
    const int b = blockIdx.x, tid = threadIdx.x, lane = tid & 31, warp = tid >> 5;
    __shared__ float sadj[196];
    __shared__ float red[4][14][8];
    if (tid < 196) sadj[tid] = g_corrn[(size_t)b * 196 + tid];
    __syncthreads();
    const float* xb = g_xw2 + (size_t)b * 14336;
    const float* xa = g_xw2 + (size_t)MROWS * 1024 + (size_t)b * 14336;
    float biasv[4];
#pragma unroll
    for (int t = 0; t < 4; t++) biasv[t] = b2[tid + t * 256];
#pragma unroll 1
    for (int i = 0; i < 14; i++) {
        float w[14];
#pragma unroll
        for (int j = 0; j < 14; j++) w[j] = sadj[i * 14 + j];
        float sc2 = 0, sh2 = 0, sc4 = 0, sh4 = 0;
        if (WRITE) {
            sc2 = g_scale[2][i]; sh2 = g_shift[2][i];
            sc4 = g_scale[3][i]; sh4 = g_shift[3][i];
        }
        float s2 = 0, q2 = 0, s4 = 0, q4 = 0;
#pragma unroll
        for (int t = 0; t < 4; t++) {
            int c = tid + t * 256;
            float a2 = biasv[t], a4 = biasv[t];
#pragma unroll
            for (int j = 0; j < 14; j++) {
                a2 = fmaf(w[j], __ldg(xb + j * 1024 + c), a2);
                a4 = fmaf(w[j], __ldg(xa + j * 1024 + c), a4);
            }
            if (WRITE) {
                out[((size_t)b * 14 + i) * 1024 + c] =
                    lrelu(fmaf(a2, sc2, sh2)) + lrelu(fmaf(a4, sc4, sh4));
            } else {
                s2 += a2; q2 = fmaf(a2, a2, q2);
                s4 += a4; q4 = fmaf(a4, a4, q4);
            }
        }
        if (!WRITE) {
            s2 = wred(s2); q2 = wred(q2); s4 = wred(s4); q4 = wred(q4);
            if (!lane) { red[0][i][warp] = s2; red[1][i][warp] = q2; red[2][i][warp] = s4; red[3][i][warp] = q4; }
        }
    }
    if (!WRITE) {
        __syncthreads();
        if (tid < 28) {
            int node = tid % 14, st = tid / 14;
            double v2 = 0, v4 = 0;
#pragma unroll
            for (int wq = 0; wq < 8; wq++) {
                v2 += (double)red[st][node][wq];
                v4 += (double)red[st + 2][node][wq];
            }
            part[(((size_t)2 * BATCH + b) * 14 + node) * 2 + st] = v2;
            part[(((size_t)3 * BATCH + b) * 14 + node) * 2 + st] = v4;
        }
    }
}

// ------------------------- deterministic BN reduce ---------------------------
__global__ __launch_bounds__(1024) void bn_reduce_kernel(
    int setA, int setB, const float* __restrict__ gA, const float* __restrict__ bA,
    const float* __restrict__ gB, const float* __restrict__ bB,
    double invCount, const double* __restrict__ part) {
    __shared__ double chunk[56][32];
    const int tid = threadIdx.x;
    for (int task = tid; task < 1792; task += 1024) {
        int series = task >> 5, ch = task & 31;
        int set = (series < 28) ? setA : setB;
        int rem = series % 28;
        int node = rem >> 1, st = rem & 1;
        double s = 0;
        int b0 = ch * 128;
        for (int bb = 0; bb < 128; bb++)
            s += part[(((size_t)set * BATCH + b0 + bb) * 14 + node) * 2 + st];
        chunk[series][ch] = s;
    }
    __syncthreads();
    if (tid < 28) {
        int setidx = tid / 14, node = tid % 14;
        int set = setidx ? setB : setA;
        double S = 0, Q = 0;
        for (int ch = 0; ch < 32; ch++) {
            S += chunk[setidx * 28 + node * 2 + 0][ch];
            Q += chunk[setidx * 28 + node * 2 + 1][ch];
        }
        double mean = S * invCount;
        double var = Q * invCount - mean * mean;
        const float* g = setidx ? gB : gA;
        const float* be = setidx ? bB : bA;
        double sc = (double)g[node] / sqrt(var + 1e-5);
        g_scale[set][node] = (float)sc;
        g_shift[set][node] = (float)((double)be[node] - mean * sc);
    }
}

// ------------------------- host launcher -------------------------------------
static void* sym_addr(const void* sym) {
    void* p = nullptr;
    cudaGetSymbolAddress(&p, sym);
    return p;
}

extern "C" void kernel_launch(void* const* d_in, const int* in_sizes, int n_in,
                              void* d_out, int out_size) {
    const float* x     = (const float*)d_in[0];
    const float* adj1  = (const float*)d_in[1];
    const float* adj2  = (const float*)d_in[2];
    const float* fc_w  = (const float*)d_in[3];
    const float* fc_b  = (const float*)d_in[4];
    const float* g1w   = (const float*)d_in[5];
    const float* g1b   = (const float*)d_in[6];
    const float* g2w   = (const float*)d_in[7];
    const float* g2b   = (const float*)d_in[8];
    const float* gamma1 = (const float*)d_in[9];
    const float* beta1  = (const float*)d_in[10];
    const float* gamma2 = (const float*)d_in[11];
    const float* beta2  = (const float*)d_in[12];
    const float* gamma3 = (const float*)d_in[13];
    const float* beta3  = (const float*)d_in[14];

    float* out      = (float*)d_out;
    float* corr_out = out + OFF_CORR;
    float* h_out    = out + OFF_H;

    __nv_bfloat16* p_xhi  = (__nv_bfloat16*)sym_addr(g_xhi);
    __nv_bfloat16* p_xlo  = (__nv_bfloat16*)sym_addr(g_xlo);
    __nv_bfloat16* p_wfch = (__nv_bfloat16*)sym_addr(g_wfc_h);
    __nv_bfloat16* p_wfcl = (__nv_bfloat16*)sym_addr(g_wfc_l);
    __nv_bfloat16* p_w1h  = (__nv_bfloat16*)sym_addr(g_w1_h);
    __nv_bfloat16* p_w1l  = (__nv_bfloat16*)sym_addr(g_w1_l);
    __nv_bfloat16* p_w2h  = (__nv_bfloat16*)sym_addr(g_w2_h);
    __nv_bfloat16* p_w2l  = (__nv_bfloat16*)sym_addr(g_w2_l);
    float*  p_xw1  = (float*)sym_addr(g_xw1);
    float*  p_pre1 = (float*)sym_addr(g_pre1);
    float*  p_pre3 = (float*)sym_addr(g_pre3);
    float*  p_xw2  = (float*)sym_addr(g_xw2);
    double* p_part = (double*)sym_addr(g_part);

    cudaFuncSetAttribute(hgemm_k<1024, 1024, true >, cudaFuncAttributeMaxDynamicSharedMemorySize, HSMEM);
    cudaFuncSetAttribute(hgemm_k<1024,  512, false>, cudaFuncAttributeMaxDynamicSharedMemorySize, HSMEM);
    cudaFuncSetAttribute(hgemm_k< 512, 1024, false>, cudaFuncAttributeMaxDynamicSharedMemorySize, HSMEM);

    prep_adj<<<1, 196>>>(adj1, adj2);

    wsplit_k<<<(1024 * 1024 + 255) / 256, 256>>>(fc_w, p_wfch, p_wfcl, 1024, 1024);
    wsplit_k<<<(512 * 1024 + 255) / 256, 256>>>(g1w, p_w1h, p_w1l, 1024, 512);
    wsplit_k<<<(1024 * 512 + 255) / 256, 256>>>(g2w, p_w2h, p_w2l, 512, 1024);

    {
        int n4 = MROWS * 1024 / 4;
        xsplit_k<<<(n4 + 255) / 256, 256>>>((const float4*)x,
                                            (__nv_bfloat162*)p_xhi, (__nv_bfloat162*)p_xlo, n4);
    }

    // h = lrelu(x @ fc_w + fc_b)
    hgemm_k<1024, 1024, true><<<dim3(4, 448), 256, HSMEM>>>(p_xhi, p_xlo, p_wfch, p_wfcl, fc_b, h_out);
    corr_kernel<<<BATCH, 256>>>(h_out, corr_out);

    // xw1 = x @ gcn1_w
    hgemm_k<1024, 512, false><<<dim3(2, 448), 256, HSMEM>>>(p_xhi, p_xlo, p_w1h, p_w1l, nullptr, p_xw1);
    agg1_kernel<<<BATCH, 128>>>(g1b, p_part);
    bn_reduce_kernel<<<1, 1024>>>(0, 1, gamma1, beta1, gamma3, beta3,
                                  1.0 / ((double)BATCH * HID), p_part);

    {
        int n4 = MROWS * 512 / 4;
        bnsplit_k<<<(n4 + 255) / 256, 256>>>((const float4*)p_pre1,
                                             (__nv_bfloat162*)p_xhi, (__nv_bfloat162*)p_xlo, 0, n4);
        bnsplit_k<<<(n4 + 255) / 256, 256>>>((const float4*)p_pre3,
                                             (__nv_bfloat162*)(p_xhi + (size_t)MROWS * 512),
                                             (__nv_bfloat162*)(p_xlo + (size_t)MROWS * 512), 1, n4);
    }

    // stacked GEMM: [cvt(pre1); cvt(pre3)] @ gcn2_w -> g_xw2 (2*MROWS x 1024)
    hgemm_k<512, 1024, false><<<dim3(4, 896), 256, HSMEM>>>(p_xhi, p_xlo, p_w2h, p_w2l, nullptr, p_xw2);

    agg2_kernel<false><<<BATCH, 256>>>(g2b, p_part, nullptr);
    bn_reduce_kernel<<<1, 1024>>>(2, 3, gamma2, beta2, gamma2, beta2,
                                  1.0 / ((double)BATCH * FOUT), p_part);
    agg2_kernel<true><<<BATCH, 256>>>(g2b, p_part, out);

    (void)in_sizes; (void)n_in; (void)out_size;
}

// round 7
// speedup vs baseline: 2.6041x; 1.2859x over previous
#include <cuda_runtime.h>
#include <cuda_fp16.h>
#include <cstddef>
#include <cstdint>

#define N_NODES 14
#define BATCH   4096
#define FIN     1024
#define FOUT    1024
#define HID     512
#define MROWS   (BATCH * N_NODES)        /* 57344 */

#define SZ_FINAL (MROWS * FOUT)
#define SZ_CORR  (BATCH * N_NODES * N_NODES)
#define OFF_CORR SZ_FINAL
#define OFF_H    (OFF_CORR + SZ_CORR)

#define WSCALE   256.0f
#define WSCALE_I (1.0f / 256.0f)

// ------------------------- device scratch -----------------------------------
__device__ __align__(256) __half g_wfc_h[1024 * 1024];
__device__ __align__(256) __half g_wfc_l[1024 * 1024];
__device__ __align__(256) __half g_w1_h[512 * 1024];
__device__ __align__(256) __half g_w1_l[512 * 1024];
__device__ __align__(256) __half g_w2_h[1024 * 512];
__device__ __align__(256) __half g_w2_l[1024 * 512];
__device__ float  g_A1n[196];
__device__ float  g_A2n[196];
__device__ float  g_xw1 [MROWS * HID];
__device__ float  g_pre1[MROWS * HID];
__device__ float  g_pre3[MROWS * HID];
__device__ float  g_xw2[2u * MROWS * FOUT];   // stacked [from pre1 ; from pre3]
__device__ float  g_corrn[BATCH * 196];
__device__ double g_part[4 * BATCH * 14 * 2];
__device__ float  g_scale[4][14];
__device__ float  g_shift[4][14];

__device__ __forceinline__ float lrelu(float v) { return v > 0.f ? v : 0.2f * v; }

__device__ __forceinline__ float wred(float v) {
#pragma unroll
    for (int o = 16; o; o >>= 1) v += __shfl_xor_sync(0xffffffffu, v, o);
    return v;
}

// ------------------------- adjacency prep -----------------------------------
__global__ void prep_adj(const float* __restrict__ adj1, const float* __restrict__ adj2) {
    __shared__ float a[2][196];
    __shared__ float dv[2][14];
    int t = threadIdx.x;                 // 196 threads
    int i = t / 14, j = t % 14;
    a[0][t] = (i == j) ? 1.f : adj1[t];
    a[1][t] = (i == j) ? 1.f : adj2[t];
    __syncthreads();
    if (t < 28) {
        int s = t / 14, r = t % 14;
        float acc = 0.f;
        for (int c = 0; c < 14; c++) acc += a[s][r * 14 + c];
        dv[s][r] = 1.f / sqrtf(fmaxf(acc, 1.f));
    }
    __syncthreads();
    g_A1n[t] = dv[0][i] * a[0][t] * dv[0][j];
    g_A2n[t] = dv[1][i] * a[1][t] * dv[1][j];
}

// ------------------------- weight transpose + fp16 split ---------------------
// W[K][Nw] fp32 -> (W*256)^T hi/lo fp16, stored [Nw][K]
__global__ void wsplit_k(const float* __restrict__ W, __half* __restrict__ th,
                         __half* __restrict__ tl, int K, int Nw) {
    int idx = blockIdx.x * 256 + threadIdx.x;
    if (idx >= K * Nw) return;
    int n = idx / K, k = idx % K;
    float v = W[(size_t)k * Nw + n] * WSCALE;
    __half h = __float2half(v);
    th[idx] = h;
    tl[idx] = __float2half(v - __half2float(h));
}

// ------------------------- fp16 2-term tensor-core GEMM ----------------------
__device__ __forceinline__ void cpa16(uint32_t dst, const void* src) {
    asm volatile("cp.async.cg.shared.global [%0], [%1], 16;\n" :: "r"(dst), "l"(src));
}
__device__ __forceinline__ void ldm_x4(uint32_t& r0, uint32_t& r1, uint32_t& r2, uint32_t& r3, uint32_t a) {
    asm volatile("ldmatrix.sync.aligned.m8n8.x4.shared.b16 {%0,%1,%2,%3},[%4];\n"
                 : "=r"(r0), "=r"(r1), "=r"(r2), "=r"(r3) : "r"(a));
}
__device__ __forceinline__ void mma_f16(float* c, const uint32_t* a, uint32_t b0, uint32_t b1) {
    asm volatile("mma.sync.aligned.m16n8k16.row.col.f32.f16.f16.f32 "
                 "{%0,%1,%2,%3},{%4,%5,%6,%7},{%8,%9},{%0,%1,%2,%3};\n"
                 : "+f"(c[0]), "+f"(c[1]), "+f"(c[2]), "+f"(c[3])
                 : "r"(a[0]), "r"(a[1]), "r"(a[2]), "r"(a[3]), "r"(b0), "r"(b1));
}

#define SPITCH 40                        /* halves: 80B rows, odd 16B stride */
#define A_SZ   (128 * SPITCH * 2)        /* 10240 B (A hi only) */
#define B_SZ   (256 * SPITCH * 2)        /* 20480 B per B matrix */
#define STG    (A_SZ + 2 * B_SZ)         /* 51200 B per stage */
#define HSMEM  (2 * STG)                 /* 102400 B */

// C[M x NTOT] = op(A_f32) @ ((Bh+Bl)/256)^T ; B stored [NTOT][KTOT] fp16.
// BN: A element -> lrelu(a*scale[preset][row%14] + shift[...]) before convert.
// Tile 128 x 256, 256 threads, warp tile 32 x 128.
template <int KTOT, int NTOT, bool BN, bool EPI>
__global__ __launch_bounds__(256, 1)
void hgemm2_k(const float* __restrict__ A, const __half* __restrict__ Bh,
              const __half* __restrict__ Bl, const float* __restrict__ bias,
              float* __restrict__ C, int preset) {
    extern __shared__ char dsm[];
    const uint32_t sbase = (uint32_t)__cvta_generic_to_shared(dsm);
    const int tid = threadIdx.x, lane = tid & 31, wid = tid >> 5;
    const int bx = blockIdx.x, by = blockIdx.y;
    const int wm = wid & 3, wn = wid >> 2;

    // A-chunk geometry: idx = tid + q*256 -> r = idx>>3, c4 = idx&7
    const int ar = tid >> 3, ac4 = tid & 7;

    float psc[4], psh[4];
    if (BN) {
#pragma unroll
        for (int q = 0; q < 4; q++) {
            int node = (by * 128 + ar + q * 32) % N_NODES;
            psc[q] = g_scale[preset][node];
            psh[q] = g_shift[preset][node];
        }
    }

    float acc[2][16][4];
#pragma unroll
    for (int i = 0; i < 2; i++)
#pragma unroll
        for (int j = 0; j < 16; j++)
#pragma unroll
            for (int q = 0; q < 4; q++) acc[i][j][q] = 0.f;

    const int NK = KTOT / 32;

#define LOAD_A(KT, AV) do {                                                    \
        _Pragma("unroll")                                                      \
        for (int q_ = 0; q_ < 4; q_++)                                         \
            (AV)[q_] = *(const float4*)(A +                                    \
                (size_t)(by * 128 + ar + q_ * 32) * KTOT + (KT) * 32 + ac4 * 4);\
    } while (0)

#define STORE_A(AV, S) do {                                                    \
        char* sd_ = dsm + (S) * STG;                                           \
        _Pragma("unroll")                                                      \
        for (int q_ = 0; q_ < 4; q_++) {                                       \
            float4 v_ = (AV)[q_];                                              \
            if (BN) {                                                          \
                v_.x = lrelu(fmaf(v_.x, psc[q_], psh[q_]));                    \
                v_.y = lrelu(fmaf(v_.y, psc[q_], psh[q_]));                    \
                v_.z = lrelu(fmaf(v_.z, psc[q_], psh[q_]));                    \
                v_.w = lrelu(fmaf(v_.w, psc[q_], psh[q_]));                    \
            }                                                                  \
            __half2 p0_ = __floats2half2_rn(v_.x, v_.y);                       \
            __half2 p1_ = __floats2half2_rn(v_.z, v_.w);                       \
            uint2 pk_;                                                         \
            pk_.x = *(uint32_t*)&p0_;                                          \
            pk_.y = *(uint32_t*)&p1_;                                          \
            *(uint2*)(sd_ + (ar + q_ * 32) * 80 + ac4 * 8) = pk_;              \
        }                                                                      \
    } while (0)

#define FILL_B(KT, S) do {                                                     \
        const uint32_t sb_ = sbase + (S) * STG + A_SZ;                         \
        const int k0_ = (KT) * 32;                                             \
        _Pragma("unroll")                                                      \
        for (int q_ = 0; q_ < 8; q_++) {                                       \
            int idx = tid + q_ * 256;                                          \
            int m = idx >> 10, r = (idx >> 2) & 255, c = idx & 3;              \
            const __half* s_ = (m ? Bl : Bh) +                                 \
                (size_t)(bx * 256 + r) * KTOT + k0_ + c * 8;                   \
            cpa16(sb_ + m * B_SZ + r * 80u + c * 16u, s_);                     \
        }                                                                      \
        asm volatile("cp.async.commit_group;\n");                              \
    } while (0)

    {
        float4 av0[4];
        LOAD_A(0, av0);
        FILL_B(0, 0);
        STORE_A(av0, 0);
    }

    float4 av[4];
    for (int kt = 0; kt < NK; kt++) {
        const bool hasNext = (kt + 1 < NK);
        if (hasNext) {
            LOAD_A(kt + 1, av);
            FILL_B(kt + 1, (kt + 1) & 1);
            asm volatile("cp.async.wait_group 1;\n");
        } else {
            asm volatile("cp.async.wait_group 0;\n");
        }
        __syncthreads();

        const uint32_t st = sbase + (kt & 1) * STG;
        const uint32_t stA = st, stB = st + A_SZ;
#pragma unroll
        for (int khalf = 0; khalf < 32; khalf += 16) {
            uint32_t ah[2][4];
#pragma unroll
            for (int ms = 0; ms < 2; ms++) {
                int row  = wm * 32 + ms * 16 + ((lane >> 3) & 1) * 8 + (lane & 7);
                int kcol = khalf + (lane >> 4) * 8;
                uint32_t off = (uint32_t)(row * SPITCH + kcol) * 2;
                ldm_x4(ah[ms][0], ah[ms][1], ah[ms][2], ah[ms][3], stA + off);
            }
#pragma unroll
            for (int np = 0; np < 8; np++) {
                int nrow = wn * 128 + np * 16 + (lane >> 4) * 8 + (lane & 7);
                int kcol = khalf + ((lane >> 3) & 1) * 8;
                uint32_t off = (uint32_t)(nrow * SPITCH + kcol) * 2;
                uint32_t bh[4], bl[4];
                ldm_x4(bh[0], bh[1], bh[2], bh[3], stB + off);
                ldm_x4(bl[0], bl[1], bl[2], bl[3], stB + B_SZ + off);
#pragma unroll
                for (int ms = 0; ms < 2; ms++)
#pragma unroll
                    for (int q = 0; q < 2; q++) {
                        float* cacc = acc[ms][np * 2 + q];
                        mma_f16(cacc, ah[ms], bh[2 * q], bh[2 * q + 1]);
                        mma_f16(cacc, ah[ms], bl[2 * q], bl[2 * q + 1]);
                    }
            }
        }
        if (hasNext) STORE_A(av, (kt + 1) & 1);
        __syncthreads();
    }
#undef FILL_B
#undef STORE_A
#undef LOAD_A

    // epilogue (unscale by 1/256, then optional bias+lrelu)
    const int rbase = by * 128 + wm * 32;
    const int cbase = bx * 256 + wn * 128;
    const int rq = lane >> 2, cq = (lane & 3) * 2;
#pragma unroll
    for (int ms = 0; ms < 2; ms++)
#pragma unroll
        for (int ns = 0; ns < 16; ns++) {
            int r0  = rbase + ms * 16 + rq;
            int col = cbase + ns * 8 + cq;
            float v0 = acc[ms][ns][0] * WSCALE_I, v1 = acc[ms][ns][1] * WSCALE_I;
            float v2 = acc[ms][ns][2] * WSCALE_I, v3 = acc[ms][ns][3] * WSCALE_I;
            if (EPI) {
                float b0 = bias[col], b1 = bias[col + 1];
                v0 = lrelu(v0 + b0); v1 = lrelu(v1 + b1);
                v2 = lrelu(v2 + b0); v3 = lrelu(v3 + b1);
            }
            *(float2*)&C[(size_t)r0 * NTOT + col]       = make_float2(v0, v1);
            *(float2*)&C[(size_t)(r0 + 8) * NTOT + col] = make_float2(v2, v3);
        }
}

// ------------------------- correlation kernel --------------------------------
__global__ __launch_bounds__(256) void corr_kernel(const float* __restrict__ h,
                                                   float* __restrict__ corr_out) {
    const int b = blockIdx.x;
    const float* hb = h + (size_t)b * N_NODES * FOUT;
    const int tid = threadIdx.x, lane = tid & 31, warp = tid >> 5;
    __shared__ float rn[14];
    __shared__ float cmat[196];
    __shared__ float dd[14];

    for (int i = warp; i < 14; i += 8) {
        float s = 0.f;
        for (int c = lane; c < FOUT; c += 32) {
            float v = __ldg(hb + i * FOUT + c);
            s = fmaf(v, v, s);
        }
        s = wred(s);
        if (!lane) rn[i] = rsqrtf(fmaxf(s, 1e-16f));
    }
    __syncthreads();

    for (int p = warp; p < 91; p += 8) {
        int i = 0, rem = p;
        while (rem >= 13 - i) { rem -= 13 - i; i++; }
        int j = i + 1 + rem;
        float s = 0.f;
        for (int c = lane; c < FOUT; c += 32)
            s = fmaf(__ldg(hb + i * FOUT + c), __ldg(hb + j * FOUT + c), s);
        s = wred(s);
        if (!lane) {
            float v = fabsf(s * rn[i] * rn[j]);
            cmat[i * 14 + j] = v;
            cmat[j * 14 + i] = v;
        }
    }
    if (tid < 14) cmat[tid * 14 + tid] = 1.f;
    __syncthreads();
    if (tid < 14) {
        float s = 0.f;
        for (int j = 0; j < 14; j++) s += cmat[tid * 14 + j];
        dd[tid] = 1.f / sqrtf(fmaxf(s, 1.f));
    }
    __syncthreads();
    if (tid < 196) {
        int i = tid / 14, j = tid % 14;
        corr_out[(size_t)b * 196 + tid] = cmat[tid];
        g_corrn[(size_t)b * 196 + tid] = dd[i] * cmat[tid] * dd[j];
    }
}

// ------------------------- branch-1 aggregation + BN stats -------------------
__global__ __launch_bounds__(128) void agg1_kernel(const float* __restrict__ b1,
                                                   double* __restrict__ part) {
    const int b = blockIdx.x, tid = threadIdx.x, lane = tid & 31, warp = tid >> 5;
    __shared__ float sh[14 * 512];
    __shared__ float sA1[196], sA2[196];
    __shared__ float red[4][14][4];
    for (int t = tid; t < 196; t += 128) { sA1[t] = g_A1n[t]; sA2[t] = g_A2n[t]; }
    const float4* src = (const float4*)(g_xw1 + (size_t)b * 7168);
    float4* d4 = (float4*)sh;
#pragma unroll
    for (int k = 0; k < 14; k++) d4[tid + k * 128] = src[tid + k * 128];
    __syncthreads();
    float biasv[4];
#pragma unroll
    for (int t = 0; t < 4; t++) biasv[t] = b1[tid + t * 128];
    float* p1 = g_pre1 + (size_t)b * 7168;
    float* p3 = g_pre3 + (size_t)b * 7168;
#pragma unroll 1
    for (int i = 0; i < 14; i++) {
        float w1[14], w2[14];
#pragma unroll
        for (int j = 0; j < 14; j++) { w1[j] = sA1[i * 14 + j]; w2[j] = sA2[i * 14 + j]; }
        float s1 = 0, q1 = 0, s3 = 0, q3 = 0;
#pragma unroll
        for (int t = 0; t < 4; t++) {
            int c = tid + t * 128;
            float a1 = biasv[t], a3 = biasv[t];
#pragma unroll
            for (int j = 0; j < 14; j++) {
                float v = sh[j * 512 + c];
                a1 = fmaf(w1[j], v, a1);
                a3 = fmaf(w2[j], v, a3);
            }
            p1[i * 512 + c] = a1;
            p3[i * 512 + c] = a3;
            s1 += a1; q1 = fmaf(a1, a1, q1);
            s3 += a3; q3 = fmaf(a3, a3, q3);
        }
        s1 = wred(s1); q1 = wred(q1); s3 = wred(s3); q3 = wred(q3);
        if (!lane) { red[0][i][warp] = s1; red[1][i][warp] = q1; red[2][i][warp] = s3; red[3][i][warp] = q3; }
    }
    __syncthreads();
    if (tid < 28) {
        int node = tid % 14, st = tid / 14;
        double v1 = (double)red[st][node][0] + red[st][node][1] + red[st][node][2] + red[st][node][3];
        double v3 = (double)red[st + 2][node][0] + red[st + 2][node][1] + red[st + 2][node][2] + red[st + 2][node][3];
        part[(((size_t)0 * BATCH + b) * 14 + node) * 2 + st] = v1;
        part[(((size_t)1 * BATCH + b) * 14 + node) * 2 + st] = v3;
    }
}

// ------------------------- branch-2 aggregation (stats / write) --------------
template <bool WRITE>
__global__ __launch_bounds__(256) void agg2_kernel(const float* __restrict__ b2,
                                                   double* __restrict__ part,
                                                   float* __restrict__ out) {
    const int b = blockIdx.x, tid = threadIdx.x, lane = tid & 31, warp = tid >> 5;
    __shared__ float sadj[196];
    __shared__ float red[4][14][8];
    if (tid < 196) sadj[tid] = g_corrn[(size_t)b * 196 + tid];
    __syncthreads();
    const float* xb = g_xw2 + (size_t)b * 14336;
    const float* xa = g_xw2 + (size_t)MROWS * 1024 + (size_t)b * 14336;
    float biasv[4];
#pragma unroll
    for (int t = 0; t < 4; t++) biasv[t] = b2[tid + t * 256];
#pragma unroll 1
    for (int i = 0; i < 14; i++) {
        float w[14];
#pragma unroll
        for (int j = 0; j < 14; j++) w[j] = sadj[i * 14 + j];
        float sc2 = 0, sh2 = 0, sc4 = 0, sh4 = 0;
        if (WRITE) {
            sc2 = g_scale[2][i]; sh2 = g_shift[2][i];
            sc4 = g_scale[3][i]; sh4 = g_shift[3][i];
        }
        float s2 = 0, q2 = 0, s4 = 0, q4 = 0;
#pragma unroll
        for (int t = 0; t < 4; t++) {
            int c = tid + t * 256;
            float a2 = biasv[t], a4 = biasv[t];
#pragma unroll
            for (int j = 0; j < 14; j++) {
                a2 = fmaf(w[j], __ldg(xb + j * 1024 + c), a2);
                a4 = fmaf(w[j], __ldg(xa + j * 1024 + c), a4);
            }
            if (WRITE) {
                out[((size_t)b * 14 + i) * 1024 + c] =
                    lrelu(fmaf(a2, sc2, sh2)) + lrelu(fmaf(a4, sc4, sh4));
            } else {
                s2 += a2; q2 = fmaf(a2, a2, q2);
                s4 += a4; q4 = fmaf(a4, a4, q4);
            }
        }
        if (!WRITE) {
            s2 = wred(s2); q2 = wred(q2); s4 = wred(s4); q4 = wred(q4);
            if (!lane) { red[0][i][warp] = s2; red[1][i][warp] = q2; red[2][i][warp] = s4; red[3][i][warp] = q4; }
        }
    }
    if (!WRITE) {
        __syncthreads();
        if (tid < 28) {
            int node = tid % 14, st = tid / 14;
            double v2 = 0, v4 = 0;
#pragma unroll
            for (int wq = 0; wq < 8; wq++) {
                v2 += (double)red[st][node][wq];
                v4 += (double)red[st + 2][node][wq];
            }
            part[(((size_t)2 * BATCH + b) * 14 + node) * 2 + st] = v2;
            part[(((size_t)3 * BATCH + b) * 14 + node) * 2 + st] = v4;
        }
    }
}

// ------------------------- deterministic BN reduce ---------------------------
__global__ __launch_bounds__(1024) void bn_reduce_kernel(
    int setA, int setB, const float* __restrict__ gA, const float* __restrict__ bA,
    const float* __restrict__ gB, const float* __restrict__ bB,
    double invCount, const double* __restrict__ part) {
    __shared__ double chunk[56][32];
    const int tid = threadIdx.x;
    for (int task = tid; task < 1792; task += 1024) {
        int series = task >> 5, ch = task & 31;
        int set = (series < 28) ? setA : setB;
        int rem = series % 28;
        int node = rem >> 1, st = rem & 1;
        double s = 0;
        int b0 = ch * 128;
        for (int bb = 0; bb < 128; bb++)
            s += part[(((size_t)set * BATCH + b0 + bb) * 14 + node) * 2 + st];
        chunk[series][ch] = s;
    }
    __syncthreads();
    if (tid < 28) {
        int setidx = tid / 14, node = tid % 14;
        int set = setidx ? setB : setA;
        double S = 0, Q = 0;
        for (int ch = 0; ch < 32; ch++) {
            S += chunk[setidx * 28 + node * 2 + 0][ch];
            Q += chunk[setidx * 28 + node * 2 + 1][ch];
        }
        double mean = S * invCount;
        double var = Q * invCount - mean * mean;
        const float* g = setidx ? gB : gA;
        const float* be = setidx ? bB : bA;
        double sc = (double)g[node] / sqrt(var + 1e-5);
        g_scale[set][node] = (float)sc;
        g_shift[set][node] = (float)((double)be[node] - mean * sc);
    }
}

// ------------------------- host launcher -------------------------------------
static void* sym_addr(const void* sym) {
    void* p = nullptr;
    cudaGetSymbolAddress(&p, sym);
    return p;
}

extern "C" void kernel_launch(void* const* d_in, const int* in_sizes, int n_in,
                              void* d_out, int out_size) {
    const float* x     = (const float*)d_in[0];
    const float* adj1  = (const float*)d_in[1];
    const float* adj2  = (const float*)d_in[2];
    const float* fc_w  = (const float*)d_in[3];
    const float* fc_b  = (const float*)d_in[4];
    const float* g1w   = (const float*)d_in[5];
    const float* g1b   = (const float*)d_in[6];
    const float* g2w   = (const float*)d_in[7];
    const float* g2b   = (const float*)d_in[8];
    const float* gamma1 = (const float*)d_in[9];
    const float* beta1  = (const float*)d_in[10];
    const float* gamma2 = (const float*)d_in[11];
    const float* beta2  = (const float*)d_in[12];
    const float* gamma3 = (const float*)d_in[13];
    const float* beta3  = (const float*)d_in[14];

    float* out      = (float*)d_out;
    float* corr_out = out + OFF_CORR;
    float* h_out    = out + OFF_H;

    __half* p_wfch = (__half*)sym_addr(g_wfc_h);
    __half* p_wfcl = (__half*)sym_addr(g_wfc_l);
    __half* p_w1h  = (__half*)sym_addr(g_w1_h);
    __half* p_w1l  = (__half*)sym_addr(g_w1_l);
    __half* p_w2h  = (__half*)sym_addr(g_w2_h);
    __half* p_w2l  = (__half*)sym_addr(g_w2_l);
    float*  p_xw1  = (float*)sym_addr(g_xw1);
    float*  p_pre1 = (float*)sym_addr(g_pre1);
    float*  p_pre3 = (float*)sym_addr(g_pre3);
    float*  p_xw2  = (float*)sym_addr(g_xw2);
    double* p_part = (double*)sym_addr(g_part);

    cudaFuncSetAttribute(hgemm2_k<1024, 1024, false, true >, cudaFuncAttributeMaxDynamicSharedMemorySize, HSMEM);
    cudaFuncSetAttribute(hgemm2_k<1024,  512, false, false>, cudaFuncAttributeMaxDynamicSharedMemorySize, HSMEM);
    cudaFuncSetAttribute(hgemm2_k< 512, 1024, true,  false>, cudaFuncAttributeMaxDynamicSharedMemorySize, HSMEM);

    prep_adj<<<1, 196>>>(adj1, adj2);

    wsplit_k<<<(1024 * 1024 + 255) / 256, 256>>>(fc_w, p_wfch, p_wfcl, 1024, 1024);
    wsplit_k<<<(512 * 1024 + 255) / 256, 256>>>(g1w, p_w1h, p_w1l, 1024, 512);
    wsplit_k<<<(1024 * 512 + 255) / 256, 256>>>(g2w, p_w2h, p_w2l, 512, 1024);

    // h = lrelu(x @ fc_w + fc_b)
    hgemm2_k<1024, 1024, false, true><<<dim3(4, 448), 256, HSMEM>>>(x, p_wfch, p_wfcl, fc_b, h_out, 0);
    corr_kernel<<<BATCH, 256>>>(h_out, corr_out);

    // xw1 = x @ gcn1_w
    hgemm2_k<1024, 512, false, false><<<dim3(2, 448), 256, HSMEM>>>(x, p_w1h, p_w1l, nullptr, p_xw1, 0);
    agg1_kernel<<<BATCH, 128>>>(g1b, p_part);
    bn_reduce_kernel<<<1, 1024>>>(0, 1, gamma1, beta1, gamma3, beta3,
                                  1.0 / ((double)BATCH * HID), p_part);

    // gcn2 GEMMs with fused BN+lrelu on the A operand
    hgemm2_k<512, 1024, true, false><<<dim3(4, 448), 256, HSMEM>>>(p_pre1, p_w2h, p_w2l, nullptr, p_xw2, 0);
    hgemm2_k<512, 1024, true, false><<<dim3(4, 448), 256, HSMEM>>>(p_pre3, p_w2h, p_w2l, nullptr,
                                                                   p_xw2 + (size_t)MROWS * 1024, 1);

    agg2_kernel<false><<<BATCH, 256>>>(g2b, p_part, nullptr);
    bn_reduce_kernel<<<1, 1024>>>(2, 3, gamma2, beta2, gamma2, beta2,
                                  1.0 / ((double)BATCH * FOUT), p_part);
    agg2_kernel<true><<<BATCH, 256>>>(g2b, p_part, out);

    (void)in_sizes; (void)n_in; (void)out_size;
}

// round 8
// speedup vs baseline: 2.9768x; 1.1431x over previous
#include <cuda_runtime.h>
#include <cuda_fp16.h>
#include <cstddef>
#include <cstdint>

#define N_NODES 14
#define BATCH   4096
#define FIN     1024
#define FOUT    1024
#define HID     512
#define MROWS   (BATCH * N_NODES)        /* 57344 */

#define SZ_FINAL (MROWS * FOUT)
#define SZ_CORR  (BATCH * N_NODES * N_NODES)
#define OFF_CORR SZ_FINAL
#define OFF_H    (OFF_CORR + SZ_CORR)

#define WSCALE   256.0f
#define WSCALE_I (1.0f / 256.0f)

// ------------------------- device scratch -----------------------------------
__device__ __align__(256) __half g_wfc_h[1024 * 1024];
__device__ __align__(256) __half g_wfc_l[1024 * 1024];
__device__ __align__(256) __half g_w1_h[512 * 1024];
__device__ __align__(256) __half g_w1_l[512 * 1024];
__device__ __align__(256) __half g_w2_h[1024 * 512];
__device__ __align__(256) __half g_w2_l[1024 * 512];
__device__ float  g_A1n[196];
__device__ float  g_A2n[196];
__device__ float  g_xw1 [MROWS * HID];
__device__ float  g_pre1[MROWS * HID];
__device__ float  g_pre3[MROWS * HID];
__device__ float  g_xw2[2u * MROWS * FOUT];   // stacked [from pre1 ; from pre3]
__device__ float  g_corrn[BATCH * 196];
__device__ double g_part[4 * BATCH * 14 * 2];
__device__ float  g_scale[4][14];
__device__ float  g_shift[4][14];

__device__ __forceinline__ float lrelu(float v) { return v > 0.f ? v : 0.2f * v; }

__device__ __forceinline__ float wred(float v) {
#pragma unroll
    for (int o = 16; o; o >>= 1) v += __shfl_xor_sync(0xffffffffu, v, o);
    return v;
}

// ------------------------- adjacency prep -----------------------------------
__global__ void prep_adj(const float* __restrict__ adj1, const float* __restrict__ adj2) {
    __shared__ float a[2][196];
    __shared__ float dv[2][14];
    int t = threadIdx.x;                 // 196 threads
    int i = t / 14, j = t % 14;
    a[0][t] = (i == j) ? 1.f : adj1[t];
    a[1][t] = (i == j) ? 1.f : adj2[t];
    __syncthreads();
    if (t < 28) {
        int s = t / 14, r = t % 14;
        float acc = 0.f;
        for (int c = 0; c < 14; c++) acc += a[s][r * 14 + c];
        dv[s][r] = 1.f / sqrtf(fmaxf(acc, 1.f));
    }
    __syncthreads();
    g_A1n[t] = dv[0][i] * a[0][t] * dv[0][j];
    g_A2n[t] = dv[1][i] * a[1][t] * dv[1][j];
}

// ------------------------- weight transpose + fp16 split ---------------------
// W[K][Nw] fp32 -> (W*256)^T hi/lo fp16, stored [Nw][K]
__global__ void wsplit_k(const float* __restrict__ W, __half* __restrict__ th,
                         __half* __restrict__ tl, int K, int Nw) {
    int idx = blockIdx.x * 256 + threadIdx.x;
    if (idx >= K * Nw) return;
    int n = idx / K, k = idx % K;
    float v = W[(size_t)k * Nw + n] * WSCALE;
    __half h = __float2half(v);
    th[idx] = h;
    tl[idx] = __float2half(v - __half2float(h));
}

// ------------------------- fp16 tensor-core GEMM -----------------------------
__device__ __forceinline__ void cpa16(uint32_t dst, const void* src) {
    asm volatile("cp.async.cg.shared.global [%0], [%1], 16;\n" :: "r"(dst), "l"(src));
}
__device__ __forceinline__ void ldm_x4(uint32_t& r0, uint32_t& r1, uint32_t& r2, uint32_t& r3, uint32_t a) {
    asm volatile("ldmatrix.sync.aligned.m8n8.x4.shared.b16 {%0,%1,%2,%3},[%4];\n"
                 : "=r"(r0), "=r"(r1), "=r"(r2), "=r"(r3) : "r"(a));
}
__device__ __forceinline__ void mma_f16(float* c, const uint32_t* a, uint32_t b0, uint32_t b1) {
    asm volatile("mma.sync.aligned.m16n8k16.row.col.f32.f16.f16.f32 "
                 "{%0,%1,%2,%3},{%4,%5,%6,%7},{%8,%9},{%0,%1,%2,%3};\n"
                 : "+f"(c[0]), "+f"(c[1]), "+f"(c[2]), "+f"(c[3])
                 : "r"(a[0]), "r"(a[1]), "r"(a[2]), "r"(a[3]), "r"(b0), "r"(b1));
}

#define SPITCH 40                        /* halves: 80B rows, odd 16B stride */
#define A_SZ   (128 * SPITCH * 2)        /* 10240 B (A hi only) */
#define B_SZ   (256 * SPITCH * 2)        /* 20480 B per B matrix */

// C[M x NTOT] = op(A_f32) @ ((Bh[+Bl])/256)^T ; B stored [NTOT][KTOT] fp16.
// BN: A element -> lrelu(a*scale[preset][row%14] + shift[...]) before convert.
// Tile 128 x 256, 256 threads, warp tile 32 x 128. TERMS = 1 or 2.
template <int KTOT, int NTOT, bool BN, bool EPI, int TERMS>
__global__ __launch_bounds__(256)
void hgemm2_k(const float* __restrict__ A, const __half* __restrict__ Bh,
              const __half* __restrict__ Bl, const float* __restrict__ bias,
              float* __restrict__ C, int preset) {
    constexpr uint32_t BSZT = (TERMS == 2) ? 2u * B_SZ : (uint32_t)B_SZ;
    constexpr uint32_t STG  = A_SZ + BSZT;

    extern __shared__ char dsm[];
    const uint32_t sbase = (uint32_t)__cvta_generic_to_shared(dsm);
    const int tid = threadIdx.x, lane = tid & 31, wid = tid >> 5;
    const int bx = blockIdx.x, by = blockIdx.y;
    const int wm = wid & 3, wn = wid >> 2;

    const int ar = tid >> 3, ac4 = tid & 7;

    float psc[4], psh[4];
    if (BN) {
#pragma unroll
        for (int q = 0; q < 4; q++) {
            int node = (by * 128 + ar + q * 32) % N_NODES;
            psc[q] = g_scale[preset][node];
            psh[q] = g_shift[preset][node];
        }
    }

    float acc[2][16][4];
#pragma unroll
    for (int i = 0; i < 2; i++)
#pragma unroll
        for (int j = 0; j < 16; j++)
#pragma unroll
            for (int q = 0; q < 4; q++) acc[i][j][q] = 0.f;

    const int NK = KTOT / 32;

#define LOAD_A(KT, AV) do {                                                    \
        _Pragma("unroll")                                                      \
        for (int q_ = 0; q_ < 4; q_++)                                         \
            (AV)[q_] = *(const float4*)(A +                                    \
                (size_t)(by * 128 + ar + q_ * 32) * KTOT + (KT) * 32 + ac4 * 4);\
    } while (0)

#define STORE_A(AV, S) do {                                                    \
        char* sd_ = dsm + (S) * STG;                                           \
        _Pragma("unroll")                                                      \
        for (int q_ = 0; q_ < 4; q_++) {                                       \
            float4 v_ = (AV)[q_];                                              \
            if (BN) {                                                          \
                v_.x = lrelu(fmaf(v_.x, psc[q_], psh[q_]));                    \
                v_.y = lrelu(fmaf(v_.y, psc[q_], psh[q_]));                    \
                v_.z = lrelu(fmaf(v_.z, psc[q_], psh[q_]));                    \
                v_.w = lrelu(fmaf(v_.w, psc[q_], psh[q_]));                    \
            }                                                                  \
            __half2 p0_ = __floats2half2_rn(v_.x, v_.y);                       \
            __half2 p1_ = __floats2half2_rn(v_.z, v_.w);                       \
            uint2 pk_;                                                         \
            pk_.x = *(uint32_t*)&p0_;                                          \
            pk_.y = *(uint32_t*)&p1_;                                          \
            *(uint2*)(sd_ + (ar + q_ * 32) * 80 + ac4 * 8) = pk_;              \
        }                                                                      \
    } while (0)

#define FILL_B(KT, S) do {                                                     \
        const uint32_t sb_ = sbase + (S) * STG + A_SZ;                         \
        const int k0_ = (KT) * 32;                                             \
        _Pragma("unroll")                                                      \
        for (int q_ = 0; q_ < 4 * TERMS; q_++) {                               \
            int idx = tid + q_ * 256;                                          \
            int m = idx >> 10, r = (idx >> 2) & 255, c = idx & 3;              \
            const __half* s_ = (m ? Bl : Bh) +                                 \
                (size_t)(bx * 256 + r) * KTOT + k0_ + c * 8;                   \
            cpa16(sb_ + m * B_SZ + r * 80u + c * 16u, s_);                     \
        }                                                                      \
        asm volatile("cp.async.commit_group;\n");                              \
    } while (0)

    {
        float4 av0[4];
        LOAD_A(0, av0);
        FILL_B(0, 0);
        STORE_A(av0, 0);
    }

    float4 av[4];
    for (int kt = 0; kt < NK; kt++) {
        const bool hasNext = (kt + 1 < NK);
        if (hasNext) {
            LOAD_A(kt + 1, av);
            FILL_B(kt + 1, (kt + 1) & 1);
            asm volatile("cp.async.wait_group 1;\n");
        } else {
            asm volatile("cp.async.wait_group 0;\n");
        }
        __syncthreads();

        const uint32_t st = sbase + (kt & 1) * STG;
        const uint32_t stA = st, stB = st + A_SZ;
#pragma unroll
        for (int khalf = 0; khalf < 32; khalf += 16) {
            uint32_t ah[2][4];
#pragma unroll
            for (int ms = 0; ms < 2; ms++) {
                int row  = wm * 32 + ms * 16 + ((lane >> 3) & 1) * 8 + (lane & 7);
                int kcol = khalf + (lane >> 4) * 8;
                uint32_t off = (uint32_t)(row * SPITCH + kcol) * 2;
                ldm_x4(ah[ms][0], ah[ms][1], ah[ms][2], ah[ms][3], stA + off);
            }
#pragma unroll
            for (int np = 0; np < 8; np++) {
                int nrow = wn * 128 + np * 16 + (lane >> 4) * 8 + (lane & 7);
                int kcol = khalf + ((lane >> 3) & 1) * 8;
                uint32_t off = (uint32_t)(nrow * SPITCH + kcol) * 2;
                uint32_t bh[4], bl[4];
                ldm_x4(bh[0], bh[1], bh[2], bh[3], stB + off);
                if (TERMS == 2) ldm_x4(bl[0], bl[1], bl[2], bl[3], stB + B_SZ + off);
#pragma unroll
                for (int ms = 0; ms < 2; ms++)
#pragma unroll
                    for (int q = 0; q < 2; q++) {
                        float* cacc = acc[ms][np * 2 + q];
                        mma_f16(cacc, ah[ms], bh[2 * q], bh[2 * q + 1]);
                        if (TERMS == 2) mma_f16(cacc, ah[ms], bl[2 * q], bl[2 * q + 1]);
                    }
            }
        }
        if (hasNext) STORE_A(av, (kt + 1) & 1);
        __syncthreads();
    }
#undef FILL_B
#undef STORE_A
#undef LOAD_A

    // epilogue (unscale by 1/256, then optional bias+lrelu)
    const int rbase = by * 128 + wm * 32;
    const int cbase = bx * 256 + wn * 128;
    const int rq = lane >> 2, cq = (lane & 3) * 2;
#pragma unroll
    for (int ms = 0; ms < 2; ms++)
#pragma unroll
        for (int ns = 0; ns < 16; ns++) {
            int r0  = rbase + ms * 16 + rq;
            int col = cbase + ns * 8 + cq;
            float v0 = acc[ms][ns][0] * WSCALE_I, v1 = acc[ms][ns][1] * WSCALE_I;
            float v2 = acc[ms][ns][2] * WSCALE_I, v3 = acc[ms][ns][3] * WSCALE_I;
            if (EPI) {
                float b0 = bias[col], b1 = bias[col + 1];
                v0 = lrelu(v0 + b0); v1 = lrelu(v1 + b1);
                v2 = lrelu(v2 + b0); v3 = lrelu(v3 + b1);
            }
            *(float2*)&C[(size_t)r0 * NTOT + col]       = make_float2(v0, v1);
            *(float2*)&C[(size_t)(r0 + 8) * NTOT + col] = make_float2(v2, v3);
        }
}

// ------------------------- correlation kernel --------------------------------
__global__ __launch_bounds__(256) void corr_kernel(const float* __restrict__ h,
                                                   float* __restrict__ corr_out) {
    const int b = blockIdx.x;
    const float* hb = h + (size_t)b * N_NODES * FOUT;
    const int tid = threadIdx.x, lane = tid & 31, warp = tid >> 5;
    __shared__ float rn[14];
    __shared__ float cmat[196];
    __shared__ float dd[14];

    for (int i = warp; i < 14; i += 8) {
        float s = 0.f;
        for (int c = lane; c < FOUT; c += 32) {
            float v = __ldg(hb + i * FOUT + c);
            s = fmaf(v, v, s);
        }
        s = wred(s);
        if (!lane) rn[i] = rsqrtf(fmaxf(s, 1e-16f));
    }
    __syncthreads();

    for (int p = warp; p < 91; p += 8) {
        int i = 0, rem = p;
        while (rem >= 13 - i) { rem -= 13 - i; i++; }
        int j = i + 1 + rem;
        float s = 0.f;
        for (int c = lane; c < FOUT; c += 32)
            s = fmaf(__ldg(hb + i * FOUT + c), __ldg(hb + j * FOUT + c), s);
        s = wred(s);
        if (!lane) {
            float v = fabsf(s * rn[i] * rn[j]);
            cmat[i * 14 + j] = v;
            cmat[j * 14 + i] = v;
        }
    }
    if (tid < 14) cmat[tid * 14 + tid] = 1.f;
    __syncthreads();
    if (tid < 14) {
        float s = 0.f;
        for (int j = 0; j < 14; j++) s += cmat[tid * 14 + j];
        dd[tid] = 1.f / sqrtf(fmaxf(s, 1.f));
    }
    __syncthreads();
    if (tid < 196) {
        int i = tid / 14, j = tid % 14;
        corr_out[(size_t)b * 196 + tid] = cmat[tid];
        g_corrn[(size_t)b * 196 + tid] = dd[i] * cmat[tid] * dd[j];
    }
}

// ------------------------- branch-1 aggregation + BN stats -------------------
__global__ __launch_bounds__(128) void agg1_kernel(const float* __restrict__ b1,
                                                   double* __restrict__ part) {
    const int b = blockIdx.x, tid = threadIdx.x, lane = tid & 31, warp = tid >> 5;
    __shared__ float sh[14 * 512];
    __shared__ float sA1[196], sA2[196];
    __shared__ float red[4][14][4];
    for (int t = tid; t < 196; t += 128) { sA1[t] = g_A1n[t]; sA2[t] = g_A2n[t]; }
    const float4* src = (const float4*)(g_xw1 + (size_t)b * 7168);
    float4* d4 = (float4*)sh;
#pragma unroll
    for (int k = 0; k < 14; k++) d4[tid + k * 128] = src[tid + k * 128];
    __syncthreads();
    float biasv[4];
#pragma unroll
    for (int t = 0; t < 4; t++) biasv[t] = b1[tid + t * 128];
    float* p1 = g_pre1 + (size_t)b * 7168;
    float* p3 = g_pre3 + (size_t)b * 7168;
#pragma unroll 1
    for (int i = 0; i < 14; i++) {
        float w1[14], w2[14];
#pragma unroll
        for (int j = 0; j < 14; j++) { w1[j] = sA1[i * 14 + j]; w2[j] = sA2[i * 14 + j]; }
        float s1 = 0, q1 = 0, s3 = 0, q3 = 0;
#pragma unroll
        for (int t = 0; t < 4; t++) {
            int c = tid + t * 128;
            float a1 = biasv[t], a3 = biasv[t];
#pragma unroll
            for (int j = 0; j < 14; j++) {
                float v = sh[j * 512 + c];
                a1 = fmaf(w1[j], v, a1);
                a3 = fmaf(w2[j], v, a3);
            }
            p1[i * 512 + c] = a1;
            p3[i * 512 + c] = a3;
            s1 += a1; q1 = fmaf(a1, a1, q1);
            s3 += a3; q3 = fmaf(a3, a3, q3);
        }
        s1 = wred(s1); q1 = wred(q1); s3 = wred(s3); q3 = wred(q3);
        if (!lane) { red[0][i][warp] = s1; red[1][i][warp] = q1; red[2][i][warp] = s3; red[3][i][warp] = q3; }
    }
    __syncthreads();
    if (tid < 28) {
        int node = tid % 14, st = tid / 14;
        double v1 = (double)red[st][node][0] + red[st][node][1] + red[st][node][2] + red[st][node][3];
        double v3 = (double)red[st + 2][node][0] + red[st + 2][node][1] + red[st + 2][node][2] + red[st + 2][node][3];
        part[(((size_t)0 * BATCH + b) * 14 + node) * 2 + st] = v1;
        part[(((size_t)1 * BATCH + b) * 14 + node) * 2 + st] = v3;
    }
}

// ------------------------- branch-2 aggregation (stats / write) --------------
template <bool WRITE>
__global__ __launch_bounds__(256) void agg2_kernel(const float* __restrict__ b2,
                                                   double* __restrict__ part,
                                                   float* __restrict__ out) {
    const int b = blockIdx.x, tid = threadIdx.x, lane = tid & 31, warp = tid >> 5;
    __shared__ float sadj[196];
    __shared__ float red[4][14][8];
    if (tid < 196) sadj[tid] = g_corrn[(size_t)b * 196 + tid];
    __syncthreads();
    const float* xb = g_xw2 + (size_t)b * 14336;
    const float* xa = g_xw2 + (size_t)MROWS * 1024 + (size_t)b * 14336;
    float biasv[4];
#pragma unroll
    for (int t = 0; t < 4; t++) biasv[t] = b2[tid + t * 256];
#pragma unroll 1
    for (int i = 0; i < 14; i++) {
        float w[14];
#pragma unroll
        for (int j = 0; j < 14; j++) w[j] = sadj[i * 14 + j];
        float sc2 = 0, sh2 = 0, sc4 = 0, sh4 = 0;
        if (WRITE) {
            sc2 = g_scale[2][i]; sh2 = g_shift[2][i];
            sc4 = g_scale[3][i]; sh4 = g_shift[3][i];
        }
        float s2 = 0, q2 = 0, s4 = 0, q4 = 0;
#pragma unroll
        for (int t = 0; t < 4; t++) {
            int c = tid + t * 256;
            float a2 = biasv[t], a4 = biasv[t];
#pragma unroll
            for (int j = 0; j < 14; j++) {
                a2 = fmaf(w[j], __ldg(xb + j * 1024 + c), a2);
                a4 = fmaf(w[j], __ldg(xa + j * 1024 + c), a4);
            }
            if (WRITE) {
                out[((size_t)b * 14 + i) * 1024 + c] =
                    lrelu(fmaf(a2, sc2, sh2)) + lrelu(fmaf(a4, sc4, sh4));
            } else {
                s2 += a2; q2 = fmaf(a2, a2, q2);
                s4 += a4; q4 = fmaf(a4, a4, q4);
            }
        }
        if (!WRITE) {
            s2 = wred(s2); q2 = wred(q2); s4 = wred(s4); q4 = wred(q4);
            if (!lane) { red[0][i][warp] = s2; red[1][i][warp] = q2; red[2][i][warp] = s4; red[3][i][warp] = q4; }
        }
    }
    if (!WRITE) {
        __syncthreads();
        if (tid < 28) {
            int node = tid % 14, st = tid / 14;
            double v2 = 0, v4 = 0;
#pragma unroll
            for (int wq = 0; wq < 8; wq++) {
                v2 += (double)red[st][node][wq];
                v4 += (double)red[st + 2][node][wq];
            }
            part[(((size_t)2 * BATCH + b) * 14 + node) * 2 + st] = v2;
            part[(((size_t)3 * BATCH + b) * 14 + node) * 2 + st] = v4;
        }
    }
}

// ------------------------- deterministic BN reduce ---------------------------
__global__ __launch_bounds__(1024) void bn_reduce_kernel(
    int setA, int setB, const float* __restrict__ gA, const float* __restrict__ bA,
    const float* __restrict__ gB, const float* __restrict__ bB,
    double invCount, const double* __restrict__ part) {
    __shared__ double chunk[56][32];
    const int tid = threadIdx.x;
    for (int task = tid; task < 1792; task += 1024) {
        int series = task >> 5, ch = task & 31;
        int set = (series < 28) ? setA : setB;
        int rem = series % 28;
        int node = rem >> 1, st = rem & 1;
        double s = 0;
        int b0 = ch * 128;
        for (int bb = 0; bb < 128; bb++)
            s += part[(((size_t)set * BATCH + b0 + bb) * 14 + node) * 2 + st];
        chunk[series][ch] = s;
    }
    __syncthreads();
    if (tid < 28) {
        int setidx = tid / 14, node = tid % 14;
        int set = setidx ? setB : setA;
        double S = 0, Q = 0;
        for (int ch = 0; ch < 32; ch++) {
            S += chunk[setidx * 28 + node * 2 + 0][ch];
            Q += chunk[setidx * 28 + node * 2 + 1][ch];
        }
        double mean = S * invCount;
        double var = Q * invCount - mean * mean;
        const float* g = setidx ? gB : gA;
        const float* be = setidx ? bB : bA;
        double sc = (double)g[node] / sqrt(var + 1e-5);
        g_scale[set][node] = (float)sc;
        g_shift[set][node] = (float)((double)be[node] - mean * sc);
    }
}

// ------------------------- host launcher -------------------------------------
static void* sym_addr(const void* sym) {
    void* p = nullptr;
    cudaGetSymbolAddress(&p, sym);
    return p;
}

extern "C" void kernel_launch(void* const* d_in, const int* in_sizes, int n_in,
                              void* d_out, int out_size) {
    const float* x     = (const float*)d_in[0];
    const float* adj1  = (const float*)d_in[1];
    const float* adj2  = (const float*)d_in[2];
    const float* fc_w  = (const float*)d_in[3];
    const float* fc_b  = (const float*)d_in[4];
    const float* g1w   = (const float*)d_in[5];
    const float* g1b   = (const float*)d_in[6];
    const float* g2w   = (const float*)d_in[7];
    const float* g2b   = (const float*)d_in[8];
    const float* gamma1 = (const float*)d_in[9];
    const float* beta1  = (const float*)d_in[10];
    const float* gamma2 = (const float*)d_in[11];
    const float* beta2  = (const float*)d_in[12];
    const float* gamma3 = (const float*)d_in[13];
    const float* beta3  = (const float*)d_in[14];

    float* out      = (float*)d_out;
    float* corr_out = out + OFF_CORR;
    float* h_out    = out + OFF_H;

    __half* p_wfch = (__half*)sym_addr(g_wfc_h);
    __half* p_wfcl = (__half*)sym_addr(g_wfc_l);
    __half* p_w1h  = (__half*)sym_addr(g_w1_h);
    __half* p_w1l  = (__half*)sym_addr(g_w1_l);
    __half* p_w2h  = (__half*)sym_addr(g_w2_h);
    __half* p_w2l  = (__half*)sym_addr(g_w2_l);
    float*  p_xw1  = (float*)sym_addr(g_xw1);
    float*  p_pre1 = (float*)sym_addr(g_pre1);
    float*  p_pre3 = (float*)sym_addr(g_pre3);
    float*  p_xw2  = (float*)sym_addr(g_xw2);
    double* p_part = (double*)sym_addr(g_part);

    const int SM2 = 2 * (A_SZ + 2 * B_SZ);   // 102400 (2-term)
    const int SM1 = 2 * (A_SZ + B_SZ);       // 61440  (1-term)

    cudaFuncSetAttribute(hgemm2_k<1024, 1024, false, true,  2>, cudaFuncAttributeMaxDynamicSharedMemorySize, SM2);
    cudaFuncSetAttribute(hgemm2_k<1024,  512, false, false, 1>, cudaFuncAttributeMaxDynamicSharedMemorySize, SM1);
    cudaFuncSetAttribute(hgemm2_k< 512, 1024, true,  false, 1>, cudaFuncAttributeMaxDynamicSharedMemorySize, SM1);

    prep_adj<<<1, 196>>>(adj1, adj2);

    wsplit_k<<<(1024 * 1024 + 255) / 256, 256>>>(fc_w, p_wfch, p_wfcl, 1024, 1024);
    wsplit_k<<<(512 * 1024 + 255) / 256, 256>>>(g1w, p_w1h, p_w1l, 1024, 512);
    wsplit_k<<<(1024 * 512 + 255) / 256, 256>>>(g2w, p_w2h, p_w2l, 512, 1024);

    // h = lrelu(x @ fc_w + fc_b)   (2-term: protects h & corr accuracy)
    hgemm2_k<1024, 1024, false, true, 2><<<dim3(4, 448), 256, SM2>>>(x, p_wfch, p_wfcl, fc_b, h_out, 0);
    corr_kernel<<<BATCH, 256>>>(h_out, corr_out);

    // xw1 = x @ gcn1_w   (1-term)
    hgemm2_k<1024, 512, false, false, 1><<<dim3(2, 448), 256, SM1>>>(x, p_w1h, p_w1l, nullptr, p_xw1, 0);
    agg1_kernel<<<BATCH, 128>>>(g1b, p_part);
    bn_reduce_kernel<<<1, 1024>>>(0, 1, gamma1, beta1, gamma3, beta3,
                                  1.0 / ((double)BATCH * HID), p_part);

    // gcn2 GEMMs with fused BN+lrelu on the A operand (1-term)
    hgemm2_k<512, 1024, true, false, 1><<<dim3(4, 448), 256, SM1>>>(p_pre1, p_w2h, p_w2l, nullptr, p_xw2, 0);
    hgemm2_k<512, 1024, true, false, 1><<<dim3(4, 448), 256, SM1>>>(p_pre3, p_w2h, p_w2l, nullptr,
                                                                    p_xw2 + (size_t)MROWS * 1024, 1);

    agg2_kernel<false><<<BATCH, 256>>>(g2b, p_part, nullptr);
    bn_reduce_kernel<<<1, 1024>>>(2, 3, gamma2, beta2, gamma2, beta2,
                                  1.0 / ((double)BATCH * FOUT), p_part);
    agg2_kernel<true><<<BATCH, 256>>>(g2b, p_part, out);

    (void)in_sizes; (void)n_in; (void)out_size;
}

// round 9
// speedup vs baseline: 3.3890x; 1.1385x over previous
#include <cuda_runtime.h>
#include <cuda_fp16.h>
#include <cstddef>
#include <cstdint>

#define N_NODES 14
#define BATCH   4096
#define FIN     1024
#define FOUT    1024
#define HID     512
#define MROWS   (BATCH * N_NODES)        /* 57344 */

#define SZ_FINAL (MROWS * FOUT)
#define SZ_CORR  (BATCH * N_NODES * N_NODES)
#define OFF_CORR SZ_FINAL
#define OFF_H    (OFF_CORR + SZ_CORR)

#define WSCALE   256.0f
#define WSCALE_I (1.0f / 256.0f)

// ------------------------- device scratch -----------------------------------
__device__ __align__(256) __half g_wfc_h[1024 * 1024];
__device__ __align__(256) __half g_wfc_l[1024 * 1024];
__device__ __align__(256) __half g_w1_h[512 * 1024];
__device__ __align__(256) __half g_w1_l[512 * 1024];
__device__ __align__(256) __half g_w2_h[1024 * 512];
__device__ __align__(256) __half g_w2_l[1024 * 512];
__device__ float  g_A1n[196];
__device__ float  g_A2n[196];
__device__ float  g_xw1 [MROWS * HID];
__device__ float  g_pre1[2u * MROWS * HID];   // stacked [pre1 ; pre3]
__device__ float  g_xw2[2u * MROWS * FOUT];   // stacked [from pre1 ; from pre3]
__device__ float  g_corrn[BATCH * 196];
__device__ double g_part[4 * BATCH * 14 * 2];
__device__ float  g_scale[4][14];
__device__ float  g_shift[4][14];

__device__ __forceinline__ float lrelu(float v) { return v > 0.f ? v : 0.2f * v; }

__device__ __forceinline__ float wred(float v) {
#pragma unroll
    for (int o = 16; o; o >>= 1) v += __shfl_xor_sync(0xffffffffu, v, o);
    return v;
}

// ------------------------- adjacency prep -----------------------------------
__global__ void prep_adj(const float* __restrict__ adj1, const float* __restrict__ adj2) {
    __shared__ float a[2][196];
    __shared__ float dv[2][14];
    int t = threadIdx.x;                 // 196 threads
    int i = t / 14, j = t % 14;
    a[0][t] = (i == j) ? 1.f : adj1[t];
    a[1][t] = (i == j) ? 1.f : adj2[t];
    __syncthreads();
    if (t < 28) {
        int s = t / 14, r = t % 14;
        float acc = 0.f;
        for (int c = 0; c < 14; c++) acc += a[s][r * 14 + c];
        dv[s][r] = 1.f / sqrtf(fmaxf(acc, 1.f));
    }
    __syncthreads();
    g_A1n[t] = dv[0][i] * a[0][t] * dv[0][j];
    g_A2n[t] = dv[1][i] * a[1][t] * dv[1][j];
}

// ------------------------- weight transpose + fp16 split ---------------------
// W[K][Nw] fp32 -> (W*256)^T hi/lo fp16, stored [Nw][K]
__global__ void wsplit_k(const float* __restrict__ W, __half* __restrict__ th,
                         __half* __restrict__ tl, int K, int Nw) {
    int idx = blockIdx.x * 256 + threadIdx.x;
    if (idx >= K * Nw) return;
    int n = idx / K, k = idx % K;
    float v = W[(size_t)k * Nw + n] * WSCALE;
    __half h = __float2half(v);
    th[idx] = h;
    tl[idx] = __float2half(v - __half2float(h));
}

// ------------------------- fp16 tensor-core GEMM -----------------------------
__device__ __forceinline__ void cpa16(uint32_t dst, const void* src) {
    asm volatile("cp.async.cg.shared.global [%0], [%1], 16;\n" :: "r"(dst), "l"(src));
}
__device__ __forceinline__ void ldm_x4(uint32_t& r0, uint32_t& r1, uint32_t& r2, uint32_t& r3, uint32_t a) {
    asm volatile("ldmatrix.sync.aligned.m8n8.x4.shared.b16 {%0,%1,%2,%3},[%4];\n"
                 : "=r"(r0), "=r"(r1), "=r"(r2), "=r"(r3) : "r"(a));
}
__device__ __forceinline__ void mma_f16(float* c, const uint32_t* a, uint32_t b0, uint32_t b1) {
    asm volatile("mma.sync.aligned.m16n8k16.row.col.f32.f16.f16.f32 "
                 "{%0,%1,%2,%3},{%4,%5,%6,%7},{%8,%9},{%0,%1,%2,%3};\n"
                 : "+f"(c[0]), "+f"(c[1]), "+f"(c[2]), "+f"(c[3])
                 : "r"(a[0]), "r"(a[1]), "r"(a[2]), "r"(a[3]), "r"(b0), "r"(b1));
}

#define SPITCH 40                        /* halves: 80B rows, odd 16B stride */
#define A_SZ   (128 * SPITCH * 2)        /* 10240 B (A hi only) */
#define B_SZ   (256 * SPITCH * 2)        /* 20480 B per B matrix */

// C[M x NTOT] = op(A_f32) @ ((Bh[+Bl])/256)^T ; B stored [NTOT][KTOT] fp16.
// BN: A -> lrelu(a*scale[preset][row%14]+shift) before convert.
// STACKED: grid.y = 896; by>=448 -> second A/C stack with preset 1.
// Tile 128 x 256, 256 threads, warp tile 32 x 128. TERMS = 1 or 2.
template <int KTOT, int NTOT, bool BN, bool EPI, int TERMS, bool STACKED>
__global__ __launch_bounds__(256)
void hgemm2_k(const float* __restrict__ A, const __half* __restrict__ Bh,
              const __half* __restrict__ Bl, const float* __restrict__ bias,
              float* __restrict__ C, int preset) {
    constexpr uint32_t BSZT = (TERMS == 2) ? 2u * B_SZ : (uint32_t)B_SZ;
    constexpr uint32_t STG  = A_SZ + BSZT;

    extern __shared__ char dsm[];
    const uint32_t sbase = (uint32_t)__cvta_generic_to_shared(dsm);
    const int tid = threadIdx.x, lane = tid & 31, wid = tid >> 5;
    const int bx = blockIdx.x;
    int by = blockIdx.y;
    const int wm = wid & 3, wn = wid >> 2;

    if (STACKED && by >= 448) {
        by -= 448;
        preset += 1;
        A += (size_t)MROWS * KTOT;
        C += (size_t)MROWS * NTOT;
    }

    const int ar = tid >> 3, ac4 = tid & 7;

    float psc[4], psh[4];
    if (BN) {
#pragma unroll
        for (int q = 0; q < 4; q++) {
            int node = (by * 128 + ar + q * 32) % N_NODES;
            psc[q] = g_scale[preset][node];
            psh[q] = g_shift[preset][node];
        }
    }

    float acc[2][16][4];
#pragma unroll
    for (int i = 0; i < 2; i++)
#pragma unroll
        for (int j = 0; j < 16; j++)
#pragma unroll
            for (int q = 0; q < 4; q++) acc[i][j][q] = 0.f;

    const int NK = KTOT / 32;

#define LOAD_A(KT, AV) do {                                                    \
        _Pragma("unroll")                                                      \
        for (int q_ = 0; q_ < 4; q_++)                                         \
            (AV)[q_] = *(const float4*)(A +                                    \
                (size_t)(by * 128 + ar + q_ * 32) * KTOT + (KT) * 32 + ac4 * 4);\
    } while (0)

#define STORE_A(AV, S) do {                                                    \
        char* sd_ = dsm + (S) * STG;                                           \
        _Pragma("unroll")                                                      \
        for (int q_ = 0; q_ < 4; q_++) {                                       \
            float4 v_ = (AV)[q_];                                              \
            if (BN) {                                                          \
                v_.x = lrelu(fmaf(v_.x, psc[q_], psh[q_]));                    \
                v_.y = lrelu(fmaf(v_.y, psc[q_], psh[q_]));                    \
                v_.z = lrelu(fmaf(v_.z, psc[q_], psh[q_]));                    \
                v_.w = lrelu(fmaf(v_.w, psc[q_], psh[q_]));                    \
            }                                                                  \
            __half2 p0_ = __floats2half2_rn(v_.x, v_.y);                       \
            __half2 p1_ = __floats2half2_rn(v_.z, v_.w);                       \
            uint2 pk_;                                                         \
            pk_.x = *(uint32_t*)&p0_;                                          \
            pk_.y = *(uint32_t*)&p1_;                                          \
            *(uint2*)(sd_ + (ar + q_ * 32) * 80 + ac4 * 8) = pk_;              \
        }                                                                      \
    } while (0)

#define FILL_B(KT, S) do {                                                     \
        const uint32_t sb_ = sbase + (S) * STG + A_SZ;                         \
        const int k0_ = (KT) * 32;                                             \
        _Pragma("unroll")                                                      \
        for (int q_ = 0; q_ < 4 * TERMS; q_++) {                               \
            int idx = tid + q_ * 256;                                          \
            int m = idx >> 10, r = (idx >> 2) & 255, c = idx & 3;              \
            const __half* s_ = (m ? Bl : Bh) +                                 \
                (size_t)(bx * 256 + r) * KTOT + k0_ + c * 8;                   \
            cpa16(sb_ + m * B_SZ + r * 80u + c * 16u, s_);                     \
        }                                                                      \
        asm volatile("cp.async.commit_group;\n");                              \
    } while (0)

    {
        float4 av0[4];
        LOAD_A(0, av0);
        FILL_B(0, 0);
        STORE_A(av0, 0);
    }

    float4 av[4];
    for (int kt = 0; kt < NK; kt++) {
        const bool hasNext = (kt + 1 < NK);
        if (hasNext) {
            LOAD_A(kt + 1, av);
            FILL_B(kt + 1, (kt + 1) & 1);
            asm volatile("cp.async.wait_group 1;\n");
        } else {
            asm volatile("cp.async.wait_group 0;\n");
        }
        __syncthreads();

        const uint32_t st = sbase + (kt & 1) * STG;
        const uint32_t stA = st, stB = st + A_SZ;
#pragma unroll
        for (int khalf = 0; khalf < 32; khalf += 16) {
            uint32_t ah[2][4];
#pragma unroll
            for (int ms = 0; ms < 2; ms++) {
                int row  = wm * 32 + ms * 16 + ((lane >> 3) & 1) * 8 + (lane & 7);
                int kcol = khalf + (lane >> 4) * 8;
                uint32_t off = (uint32_t)(row * SPITCH + kcol) * 2;
                ldm_x4(ah[ms][0], ah[ms][1], ah[ms][2], ah[ms][3], stA + off);
            }
#pragma unroll
            for (int np = 0; np < 8; np++) {
                int nrow = wn * 128 + np * 16 + (lane >> 4) * 8 + (lane & 7);
                int kcol = khalf + ((lane >> 3) & 1) * 8;
                uint32_t off = (uint32_t)(nrow * SPITCH + kcol) * 2;
                uint32_t bh[4], bl[4];
                ldm_x4(bh[0], bh[1], bh[2], bh[3], stB + off);
                if (TERMS == 2) ldm_x4(bl[0], bl[1], bl[2], bl[3], stB + B_SZ + off);
#pragma unroll
                for (int ms = 0; ms < 2; ms++)
#pragma unroll
                    for (int q = 0; q < 2; q++) {
                        float* cacc = acc[ms][np * 2 + q];
                        mma_f16(cacc, ah[ms], bh[2 * q], bh[2 * q + 1]);
                        if (TERMS == 2) mma_f16(cacc, ah[ms], bl[2 * q], bl[2 * q + 1]);
                    }
            }
        }
        if (hasNext) STORE_A(av, (kt + 1) & 1);
        __syncthreads();
    }
#undef FILL_B
#undef STORE_A
#undef LOAD_A

    // epilogue (unscale by 1/256, then optional bias+lrelu)
    const int rbase = by * 128 + wm * 32;
    const int cbase = bx * 256 + wn * 128;
    const int rq = lane >> 2, cq = (lane & 3) * 2;
#pragma unroll
    for (int ms = 0; ms < 2; ms++)
#pragma unroll
        for (int ns = 0; ns < 16; ns++) {
            int r0  = rbase + ms * 16 + rq;
            int col = cbase + ns * 8 + cq;
            float v0 = acc[ms][ns][0] * WSCALE_I, v1 = acc[ms][ns][1] * WSCALE_I;
            float v2 = acc[ms][ns][2] * WSCALE_I, v3 = acc[ms][ns][3] * WSCALE_I;
            if (EPI) {
                float b0 = bias[col], b1 = bias[col + 1];
                v0 = lrelu(v0 + b0); v1 = lrelu(v1 + b1);
                v2 = lrelu(v2 + b0); v3 = lrelu(v3 + b1);
            }
            *(float2*)&C[(size_t)r0 * NTOT + col]       = make_float2(v0, v1);
            *(float2*)&C[(size_t)(r0 + 8) * NTOT + col] = make_float2(v2, v3);
        }
}

// ------------------------- correlation kernel --------------------------------
__global__ __launch_bounds__(256) void corr_kernel(const float* __restrict__ h,
                                                   float* __restrict__ corr_out) {
    const int b = blockIdx.x;
    const float* hb = h + (size_t)b * N_NODES * FOUT;
    const int tid = threadIdx.x, lane = tid & 31, warp = tid >> 5;
    __shared__ float rn[14];
    __shared__ float cmat[196];
    __shared__ float dd[14];

    for (int i = warp; i < 14; i += 8) {
        float s = 0.f;
        for (int c = lane; c < FOUT; c += 32) {
            float v = __ldg(hb + i * FOUT + c);
            s = fmaf(v, v, s);
        }
        s = wred(s);
        if (!lane) rn[i] = rsqrtf(fmaxf(s, 1e-16f));
    }
    __syncthreads();

    for (int p = warp; p < 91; p += 8) {
        int i = 0, rem = p;
        while (rem >= 13 - i) { rem -= 13 - i; i++; }
        int j = i + 1 + rem;
        float s = 0.f;
        for (int c = lane; c < FOUT; c += 32)
            s = fmaf(__ldg(hb + i * FOUT + c), __ldg(hb + j * FOUT + c), s);
        s = wred(s);
        if (!lane) {
            float v = fabsf(s * rn[i] * rn[j]);
            cmat[i * 14 + j] = v;
            cmat[j * 14 + i] = v;
        }
    }
    if (tid < 14) cmat[tid * 14 + tid] = 1.f;
    __syncthreads();
    if (tid < 14) {
        float s = 0.f;
        for (int j = 0; j < 14; j++) s += cmat[tid * 14 + j];
        dd[tid] = 1.f / sqrtf(fmaxf(s, 1.f));
    }
    __syncthreads();
    if (tid < 196) {
        int i = tid / 14, j = tid % 14;
        corr_out[(size_t)b * 196 + tid] = cmat[tid];
        g_corrn[(size_t)b * 196 + tid] = dd[i] * cmat[tid] * dd[j];
    }
}

// ------------------------- branch-1 aggregation + BN stats -------------------
__global__ __launch_bounds__(128) void agg1_kernel(const float* __restrict__ b1,
                                                   double* __restrict__ part) {
    const int b = blockIdx.x, tid = threadIdx.x, lane = tid & 31, warp = tid >> 5;
    __shared__ float sh[14 * 512];
    __shared__ float sA1[196], sA2[196];
    __shared__ float red[4][14][4];
    for (int t = tid; t < 196; t += 128) { sA1[t] = g_A1n[t]; sA2[t] = g_A2n[t]; }
    const float4* src = (const float4*)(g_xw1 + (size_t)b * 7168);
    float4* d4 = (float4*)sh;
#pragma unroll
    for (int k = 0; k < 14; k++) d4[tid + k * 128] = src[tid + k * 128];
    __syncthreads();
    float biasv[4];
#pragma unroll
    for (int t = 0; t < 4; t++) biasv[t] = b1[tid + t * 128];
    float* p1 = g_pre1 + (size_t)b * 7168;
    float* p3 = g_pre1 + (size_t)MROWS * 512 + (size_t)b * 7168;
#pragma unroll 1
    for (int i = 0; i < 14; i++) {
        float w1[14], w2[14];
#pragma unroll
        for (int j = 0; j < 14; j++) { w1[j] = sA1[i * 14 + j]; w2[j] = sA2[i * 14 + j]; }
        float s1 = 0, q1 = 0, s3 = 0, q3 = 0;
#pragma unroll
        for (int t = 0; t < 4; t++) {
            int c = tid + t * 128;
            float a1 = biasv[t], a3 = biasv[t];
#pragma unroll
            for (int j = 0; j < 14; j++) {
                float v = sh[j * 512 + c];
                a1 = fmaf(w1[j], v, a1);
                a3 = fmaf(w2[j], v, a3);
            }
            p1[i * 512 + c] = a1;
            p3[i * 512 + c] = a3;
            s1 += a1; q1 = fmaf(a1, a1, q1);
            s3 += a3; q3 = fmaf(a3, a3, q3);
        }
        s1 = wred(s1); q1 = wred(q1); s3 = wred(s3); q3 = wred(q3);
        if (!lane) { red[0][i][warp] = s1; red[1][i][warp] = q1; red[2][i][warp] = s3; red[3][i][warp] = q3; }
    }
    __syncthreads();
    if (tid < 28) {
        int node = tid % 14, st = tid / 14;
        double v1 = (double)red[st][node][0] + red[st][node][1] + red[st][node][2] + red[st][node][3];
        double v3 = (double)red[st + 2][node][0] + red[st + 2][node][1] + red[st + 2][node][2] + red[st + 2][node][3];
        part[(((size_t)0 * BATCH + b) * 14 + node) * 2 + st] = v1;
        part[(((size_t)1 * BATCH + b) * 14 + node) * 2 + st] = v3;
    }
}

// ------------------------- branch-2 aggregation (stats / write) --------------
template <bool WRITE>
__global__ __launch_bounds__(256) void agg2_kernel(const float* __restrict__ b2,
                                                   double* __restrict__ part,
                                                   float* __restrict__ out) {
    const int b = blockIdx.x, tid = threadIdx.x, lane = tid & 31, warp = tid >> 5;
    __shared__ float sadj[196];
    __shared__ float red[4][14][8];
    if (tid < 196) sadj[tid] = g_corrn[(size_t)b * 196 + tid];
    __syncthreads();
    const float* xb = g_xw2 + (size_t)b * 14336;
    const float* xa = g_xw2 + (size_t)MROWS * 1024 + (size_t)b * 14336;
    float biasv[4];
#pragma unroll
    for (int t = 0; t < 4; t++) biasv[t] = b2[tid + t * 256];
#pragma unroll 1
    for (int i = 0; i < 14; i++) {
        float w[14];
#pragma unroll
        for (int j = 0; j < 14; j++) w[j] = sadj[i * 14 + j];
        float sc2 = 0, sh2 = 0, sc4 = 0, sh4 = 0;
        if (WRITE) {
            sc2 = g_scale[2][i]; sh2 = g_shift[2][i];
            sc4 = g_scale[3][i]; sh4 = g_shift[3][i];
        }
        float s2 = 0, q2 = 0, s4 = 0, q4 = 0;
#pragma unroll
        for (int t = 0; t < 4; t++) {
            int c = tid + t * 256;
            float a2 = biasv[t], a4 = biasv[t];
#pragma unroll
            for (int j = 0; j < 14; j++) {
                a2 = fmaf(w[j], __ldg(xb + j * 1024 + c), a2);
                a4 = fmaf(w[j], __ldg(xa + j * 1024 + c), a4);
            }
            if (WRITE) {
                out[((size_t)b * 14 + i) * 1024 + c] =
                    lrelu(fmaf(a2, sc2, sh2)) + lrelu(fmaf(a4, sc4, sh4));
            } else {
                s2 += a2; q2 = fmaf(a2, a2, q2);
                s4 += a4; q4 = fmaf(a4, a4, q4);
            }
        }
        if (!WRITE) {
            s2 = wred(s2); q2 = wred(q2); s4 = wred(s4); q4 = wred(q4);
            if (!lane) { red[0][i][warp] = s2; red[1][i][warp] = q2; red[2][i][warp] = s4; red[3][i][warp] = q4; }
        }
    }
    if (!WRITE) {
        __syncthreads();
        if (tid < 28) {
            int node = tid % 14, st = tid / 14;
            double v2 = 0, v4 = 0;
#pragma unroll
            for (int wq = 0; wq < 8; wq++) {
                v2 += (double)red[st][node][wq];
                v4 += (double)red[st + 2][node][wq];
            }
            part[(((size_t)2 * BATCH + b) * 14 + node) * 2 + st] = v2;
            part[(((size_t)3 * BATCH + b) * 14 + node) * 2 + st] = v4;
        }
    }
}

// ------------------------- deterministic BN reduce ---------------------------
__global__ __launch_bounds__(1024) void bn_reduce_kernel(
    int setA, int setB, const float* __restrict__ gA, const float* __restrict__ bA,
    const float* __restrict__ gB, const float* __restrict__ bB,
    double invCount, const double* __restrict__ part) {
    __shared__ double chunk[56][32];
    const int tid = threadIdx.x;
    for (int task = tid; task < 1792; task += 1024) {
        int series = task >> 5, ch = task & 31;
        int set = (series < 28) ? setA : setB;
        int rem = series % 28;
        int node = rem >> 1, st = rem & 1;
        double s = 0;
        int b0 = ch * 128;
        for (int bb = 0; bb < 128; bb++)
            s += part[(((size_t)set * BATCH + b0 + bb) * 14 + node) * 2 + st];
        chunk[series][ch] = s;
    }
    __syncthreads();
    if (tid < 28) {
        int setidx = tid / 14, node = tid % 14;
        int set = setidx ? setB : setA;
        double S = 0, Q = 0;
        for (int ch = 0; ch < 32; ch++) {
            S += chunk[setidx * 28 + node * 2 + 0][ch];
            Q += chunk[setidx * 28 + node * 2 + 1][ch];
        }
        double mean = S * invCount;
        double var = Q * invCount - mean * mean;
        const float* g = setidx ? gB : gA;
        const float* be = setidx ? bB : bA;
        double sc = (double)g[node] / sqrt(var + 1e-5);
        g_scale[set][node] = (float)sc;
        g_shift[set][node] = (float)((double)be[node] - mean * sc);
    }
}

// ------------------------- host launcher -------------------------------------
static void* sym_addr(const void* sym) {
    void* p = nullptr;
    cudaGetSymbolAddress(&p, sym);
    return p;
}

extern "C" void kernel_launch(void* const* d_in, const int* in_sizes, int n_in,
                              void* d_out, int out_size) {
    const float* x     = (const float*)d_in[0];
    const float* adj1  = (const float*)d_in[1];
    const float* adj2  = (const float*)d_in[2];
    const float* fc_w  = (const float*)d_in[3];
    const float* fc_b  = (const float*)d_in[4];
    const float* g1w   = (const float*)d_in[5];
    const float* g1b   = (const float*)d_in[6];
    const float* g2w   = (const float*)d_in[7];
    const float* g2b   = (const float*)d_in[8];
    const float* gamma1 = (const float*)d_in[9];
    const float* beta1  = (const float*)d_in[10];
    const float* gamma2 = (const float*)d_in[11];
    const float* beta2  = (const float*)d_in[12];
    const float* gamma3 = (const float*)d_in[13];
    const float* beta3  = (const float*)d_in[14];

    float* out      = (float*)d_out;
    float* corr_out = out + OFF_CORR;
    float* h_out    = out + OFF_H;

    __half* p_wfch = (__half*)sym_addr(g_wfc_h);
    __half* p_wfcl = (__half*)sym_addr(g_wfc_l);
    __half* p_w1h  = (__half*)sym_addr(g_w1_h);
    __half* p_w1l  = (__half*)sym_addr(g_w1_l);
    __half* p_w2h  = (__half*)sym_addr(g_w2_h);
    __half* p_w2l  = (__half*)sym_addr(g_w2_l);
    float*  p_xw1  = (float*)sym_addr(g_xw1);
    float*  p_pre1 = (float*)sym_addr(g_pre1);
    float*  p_xw2  = (float*)sym_addr(g_xw2);
    double* p_part = (double*)sym_addr(g_part);

    const int SM1 = 2 * (A_SZ + B_SZ);       // 61440  (1-term)

    cudaFuncSetAttribute(hgemm2_k<1024, 1024, false, true,  1, false>, cudaFuncAttributeMaxDynamicSharedMemorySize, SM1);
    cudaFuncSetAttribute(hgemm2_k<1024,  512, false, false, 1, false>, cudaFuncAttributeMaxDynamicSharedMemorySize, SM1);
    cudaFuncSetAttribute(hgemm2_k< 512, 1024, true,  false, 1, true >, cudaFuncAttributeMaxDynamicSharedMemorySize, SM1);

    prep_adj<<<1, 196>>>(adj1, adj2);

    wsplit_k<<<(1024 * 1024 + 255) / 256, 256>>>(fc_w, p_wfch, p_wfcl, 1024, 1024);
    wsplit_k<<<(512 * 1024 + 255) / 256, 256>>>(g1w, p_w1h, p_w1l, 1024, 512);
    wsplit_k<<<(1024 * 512 + 255) / 256, 256>>>(g2w, p_w2h, p_w2l, 512, 1024);

    // h = lrelu(x @ fc_w + fc_b)   (1-term)
    hgemm2_k<1024, 1024, false, true, 1, false><<<dim3(4, 448), 256, SM1>>>(x, p_wfch, p_wfcl, fc_b, h_out, 0);
    corr_kernel<<<BATCH, 256>>>(h_out, corr_out);

    // xw1 = x @ gcn1_w   (1-term)
    hgemm2_k<1024, 512, false, false, 1, false><<<dim3(2, 448), 256, SM1>>>(x, p_w1h, p_w1l, nullptr, p_xw1, 0);
    agg1_kernel<<<BATCH, 128>>>(g1b, p_part);
    bn_reduce_kernel<<<1, 1024>>>(0, 1, gamma1, beta1, gamma3, beta3,
                                  1.0 / ((double)BATCH * HID), p_part);

    // stacked gcn2 GEMM: by<448 -> pre1/preset0, by>=448 -> pre3/preset1
    hgemm2_k<512, 1024, true, false, 1, true><<<dim3(4, 896), 256, SM1>>>(p_pre1, p_w2h, p_w2l, nullptr, p_xw2, 0);

    agg2_kernel<false><<<BATCH, 256>>>(g2b, p_part, nullptr);
    bn_reduce_kernel<<<1, 1024>>>(2, 3, gamma2, beta2, gamma2, beta2,
                                  1.0 / ((double)BATCH * FOUT), p_part);
    agg2_kernel<true><<<BATCH, 256>>>(g2b, p_part, out);

    (void)in_sizes; (void)n_in; (void)out_size;
}

// round 10
// speedup vs baseline: 3.3924x; 1.0010x over previous
#include <cuda_runtime.h>
#include <cuda_fp16.h>
#include <cstddef>
#include <cstdint>

#define N_NODES 14
#define BATCH   4096
#define FIN     1024
#define FOUT    1024
#define HID     512
#define MROWS   (BATCH * N_NODES)        /* 57344 */

#define SZ_FINAL (MROWS * FOUT)
#define SZ_CORR  (BATCH * N_NODES * N_NODES)
#define OFF_CORR SZ_FINAL
#define OFF_H    (OFF_CORR + SZ_CORR)

#define WSCALE   256.0f
#define WSCALE_I (1.0f / 256.0f)

// ------------------------- device scratch -----------------------------------
__device__ __align__(256) __half g_wfc_h[1024 * 1024];
__device__ __align__(256) __half g_wfc_l[1024 * 1024];
__device__ __align__(256) __half g_w1_h[512 * 1024];
__device__ __align__(256) __half g_w1_l[512 * 1024];
__device__ __align__(256) __half g_w2_h[1024 * 512];
__device__ __align__(256) __half g_w2_l[1024 * 512];
__device__ float  g_A1n[196];
__device__ float  g_A2n[196];
__device__ float  g_xw1 [MROWS * HID];
__device__ float  g_pre1[2u * MROWS * HID];   // stacked [pre1 ; pre3]
__device__ float  g_xw2[2u * MROWS * FOUT];   // stacked [from pre1 ; from pre3]
__device__ float  g_corrn[BATCH * 196];
__device__ double g_part[4 * BATCH * 14 * 2];
__device__ float  g_scale[4][14];
__device__ float  g_shift[4][14];

__device__ __forceinline__ float lrelu(float v) { return v > 0.f ? v : 0.2f * v; }

__device__ __forceinline__ float wred(float v) {
#pragma unroll
    for (int o = 16; o; o >>= 1) v += __shfl_xor_sync(0xffffffffu, v, o);
    return v;
}

// ------------------------- adjacency prep -----------------------------------
__global__ void prep_adj(const float* __restrict__ adj1, const float* __restrict__ adj2) {
    __shared__ float a[2][196];
    __shared__ float dv[2][14];
    int t = threadIdx.x;                 // 196 threads
    int i = t / 14, j = t % 14;
    a[0][t] = (i == j) ? 1.f : adj1[t];
    a[1][t] = (i == j) ? 1.f : adj2[t];
    __syncthreads();
    if (t < 28) {
        int s = t / 14, r = t % 14;
        float acc = 0.f;
        for (int c = 0; c < 14; c++) acc += a[s][r * 14 + c];
        dv[s][r] = 1.f / sqrtf(fmaxf(acc, 1.f));
    }
    __syncthreads();
    g_A1n[t] = dv[0][i] * a[0][t] * dv[0][j];
    g_A2n[t] = dv[1][i] * a[1][t] * dv[1][j];
}

// ------------------------- weight transpose + fp16 split ---------------------
// W[K][Nw] fp32 -> (W*256)^T hi/lo fp16, stored [Nw][K]
__global__ void wsplit_k(const float* __restrict__ W, __half* __restrict__ th,
                         __half* __restrict__ tl, int K, int Nw) {
    int idx = blockIdx.x * 256 + threadIdx.x;
    if (idx >= K * Nw) return;
    int n = idx / K, k = idx % K;
    float v = W[(size_t)k * Nw + n] * WSCALE;
    __half h = __float2half(v);
    th[idx] = h;
    tl[idx] = __float2half(v - __half2float(h));
}

// ------------------------- fp16 tensor-core GEMM -----------------------------
__device__ __forceinline__ void cpa16(uint32_t dst, const void* src) {
    asm volatile("cp.async.cg.shared.global [%0], [%1], 16;\n" :: "r"(dst), "l"(src));
}
__device__ __forceinline__ void ldm_x4(uint32_t& r0, uint32_t& r1, uint32_t& r2, uint32_t& r3, uint32_t a) {
    asm volatile("ldmatrix.sync.aligned.m8n8.x4.shared.b16 {%0,%1,%2,%3},[%4];\n"
                 : "=r"(r0), "=r"(r1), "=r"(r2), "=r"(r3) : "r"(a));
}
__device__ __forceinline__ void mma_f16(float* c, const uint32_t* a, uint32_t b0, uint32_t b1) {
    asm volatile("mma.sync.aligned.m16n8k16.row.col.f32.f16.f16.f32 "
                 "{%0,%1,%2,%3},{%4,%5,%6,%7},{%8,%9},{%0,%1,%2,%3};\n"
                 : "+f"(c[0]), "+f"(c[1]), "+f"(c[2]), "+f"(c[3])
                 : "r"(a[0]), "r"(a[1]), "r"(a[2]), "r"(a[3]), "r"(b0), "r"(b1));
}

#define SPITCH 40                        /* halves: 80B rows, odd 16B stride */
#define A_SZ   (128 * SPITCH * 2)        /* 10240 B (A hi only) */
#define B_SZ   (256 * SPITCH * 2)        /* 20480 B per B matrix */

// C[M x NTOT] = op(A_f32) @ ((Bh[+Bl])/256)^T ; B stored [NTOT][KTOT] fp16.
// BN: A -> lrelu(a*scale[preset][row%14]+shift) before convert.
// STACKED: grid.y = 896; by>=448 -> second A/C stack with preset 1.
// Tile 128 x 256, 256 threads, warp tile 32 x 128. TERMS = 1 or 2.
template <int KTOT, int NTOT, bool BN, bool EPI, int TERMS, bool STACKED>
__global__ __launch_bounds__(256)
void hgemm2_k(const float* __restrict__ A, const __half* __restrict__ Bh,
              const __half* __restrict__ Bl, const float* __restrict__ bias,
              float* __restrict__ C, int preset) {
    constexpr uint32_t BSZT = (TERMS == 2) ? 2u * B_SZ : (uint32_t)B_SZ;
    constexpr uint32_t STG  = A_SZ + BSZT;

    extern __shared__ char dsm[];
    const uint32_t sbase = (uint32_t)__cvta_generic_to_shared(dsm);
    const int tid = threadIdx.x, lane = tid & 31, wid = tid >> 5;
    const int bx = blockIdx.x;
    int by = blockIdx.y;
    const int wm = wid & 3, wn = wid >> 2;

    if (STACKED && by >= 448) {
        by -= 448;
        preset += 1;
        A += (size_t)MROWS * KTOT;
        C += (size_t)MROWS * NTOT;
    }

    const int ar = tid >> 3, ac4 = tid & 7;

    float psc[4], psh[4];
    if (BN) {
#pragma unroll
        for (int q = 0; q < 4; q++) {
            int node = (by * 128 + ar + q * 32) % N_NODES;
            psc[q] = g_scale[preset][node];
            psh[q] = g_shift[preset][node];
        }
    }

    float acc[2][16][4];
#pragma unroll
    for (int i = 0; i < 2; i++)
#pragma unroll
        for (int j = 0; j < 16; j++)
#pragma unroll
            for (int q = 0; q < 4; q++) acc[i][j][q] = 0.f;

    const int NK = KTOT / 32;

#define LOAD_A(KT, AV) do {                                                    \
        _Pragma("unroll")                                                      \
        for (int q_ = 0; q_ < 4; q_++)                                         \
            (AV)[q_] = *(const float4*)(A +                                    \
                (size_t)(by * 128 + ar + q_ * 32) * KTOT + (KT) * 32 + ac4 * 4);\
    } while (0)

#define STORE_A(AV, S) do {                                                    \
        char* sd_ = dsm + (S) * STG;                                           \
        _Pragma("unroll")                                                      \
        for (int q_ = 0; q_ < 4; q_++) {                                       \
            float4 v_ = (AV)[q_];                                              \
            if (BN) {                                                          \
                v_.x = lrelu(fmaf(v_.x, psc[q_], psh[q_]));                    \
                v_.y = lrelu(fmaf(v_.y, psc[q_], psh[q_]));                    \
                v_.z = lrelu(fmaf(v_.z, psc[q_], psh[q_]));                    \
                v_.w = lrelu(fmaf(v_.w, psc[q_], psh[q_]));                    \
            }                                                                  \
            __half2 p0_ = __floats2half2_rn(v_.x, v_.y);                       \
            __half2 p1_ = __floats2half2_rn(v_.z, v_.w);                       \
            uint2 pk_;                                                         \
            pk_.x = *(uint32_t*)&p0_;                                          \
            pk_.y = *(uint32_t*)&p1_;                                          \
            *(uint2*)(sd_ + (ar + q_ * 32) * 80 + ac4 * 8) = pk_;              \
        }                                                                      \
    } while (0)

#define FILL_B(KT, S) do {                                                     \
        const uint32_t sb_ = sbase + (S) * STG + A_SZ;                         \
        const int k0_ = (KT) * 32;                                             \
        _Pragma("unroll")                                                      \
        for (int q_ = 0; q_ < 4 * TERMS; q_++) {                               \
            int idx = tid + q_ * 256;                                          \
            int m = idx >> 10, r = (idx >> 2) & 255, c = idx & 3;              \
            const __half* s_ = (m ? Bl : Bh) +                                 \
                (size_t)(bx * 256 + r) * KTOT + k0_ + c * 8;                   \
            cpa16(sb_ + m * B_SZ + r * 80u + c * 16u, s_);                     \
        }                                                                      \
        asm volatile("cp.async.commit_group;\n");                              \
    } while (0)

    {
        float4 av0[4];
        LOAD_A(0, av0);
        FILL_B(0, 0);
        STORE_A(av0, 0);
    }

    float4 av[4];
    for (int kt = 0; kt < NK; kt++) {
        const bool hasNext = (kt + 1 < NK);
        if (hasNext) {
            LOAD_A(kt + 1, av);
            FILL_B(kt + 1, (kt + 1) & 1);
            asm volatile("cp.async.wait_group 1;\n");
        } else {
            asm volatile("cp.async.wait_group 0;\n");
        }
        __syncthreads();

        const uint32_t st = sbase + (kt & 1) * STG;
        const uint32_t stA = st, stB = st + A_SZ;
#pragma unroll
        for (int khalf = 0; khalf < 32; khalf += 16) {
            uint32_t ah[2][4];
#pragma unroll
            for (int ms = 0; ms < 2; ms++) {
                int row  = wm * 32 + ms * 16 + ((lane >> 3) & 1) * 8 + (lane & 7);
                int kcol = khalf + (lane >> 4) * 8;
                uint32_t off = (uint32_t)(row * SPITCH + kcol) * 2;
                ldm_x4(ah[ms][0], ah[ms][1], ah[ms][2], ah[ms][3], stA + off);
            }
#pragma unroll
            for (int np = 0; np < 8; np++) {
                int nrow = wn * 128 + np * 16 + (lane >> 4) * 8 + (lane & 7);
                int kcol = khalf + ((lane >> 3) & 1) * 8;
                uint32_t off = (uint32_t)(nrow * SPITCH + kcol) * 2;
                uint32_t bh[4], bl[4];
                ldm_x4(bh[0], bh[1], bh[2], bh[3], stB + off);
                if (TERMS == 2) ldm_x4(bl[0], bl[1], bl[2], bl[3], stB + B_SZ + off);
#pragma unroll
                for (int ms = 0; ms < 2; ms++)
#pragma unroll
                    for (int q = 0; q < 2; q++) {
                        float* cacc = acc[ms][np * 2 + q];
                        mma_f16(cacc, ah[ms], bh[2 * q], bh[2 * q + 1]);
                        if (TERMS == 2) mma_f16(cacc, ah[ms], bl[2 * q], bl[2 * q + 1]);
                    }
            }
        }
        if (hasNext) STORE_A(av, (kt + 1) & 1);
        __syncthreads();
    }
#undef FILL_B
#undef STORE_A
#undef LOAD_A

    // epilogue (unscale by 1/256, then optional bias+lrelu)
    const int rbase = by * 128 + wm * 32;
    const int cbase = bx * 256 + wn * 128;
    const int rq = lane >> 2, cq = (lane & 3) * 2;
#pragma unroll
    for (int ms = 0; ms < 2; ms++)
#pragma unroll
        for (int ns = 0; ns < 16; ns++) {
            int r0  = rbase + ms * 16 + rq;
            int col = cbase + ns * 8 + cq;
            float v0 = acc[ms][ns][0] * WSCALE_I, v1 = acc[ms][ns][1] * WSCALE_I;
            float v2 = acc[ms][ns][2] * WSCALE_I, v3 = acc[ms][ns][3] * WSCALE_I;
            if (EPI) {
                float b0 = bias[col], b1 = bias[col + 1];
                v0 = lrelu(v0 + b0); v1 = lrelu(v1 + b1);
                v2 = lrelu(v2 + b0); v3 = lrelu(v3 + b1);
            }
            *(float2*)&C[(size_t)r0 * NTOT + col]       = make_float2(v0, v1);
            *(float2*)&C[(size_t)(r0 + 8) * NTOT + col] = make_float2(v2, v3);
        }
}

// ------------------------- correlation kernel (smem-staged) ------------------
__global__ __launch_bounds__(256) void corr_kernel(const float* __restrict__ h,
                                                   float* __restrict__ corr_out) {
    extern __shared__ float4 hs4[];      // 14 rows x 256 float4 = 57344 B
    __shared__ float rn[14];
    __shared__ float cmat[196];
    __shared__ float dd[14];

    const int b = blockIdx.x;
    const int tid = threadIdx.x, lane = tid & 31, warp = tid >> 5;
    const float4* hb4 = (const float4*)(h + (size_t)b * 14336);

#pragma unroll
    for (int q = 0; q < 14; q++) hs4[tid + q * 256] = hb4[tid + q * 256];
    __syncthreads();

    // two passes: pass 0 -> i = warp (0..7); pass 1 -> i = 8 + warp (warps 0..5)
#pragma unroll 1
    for (int pass = 0; pass < 2; pass++) {
        int i = pass * 8 + warp;
        if (i < 14) {
            float4 ri[8];
#pragma unroll
            for (int k = 0; k < 8; k++) ri[k] = hs4[i * 256 + lane + 32 * k];
            float s = 0.f;
#pragma unroll
            for (int k = 0; k < 8; k++) {
                s = fmaf(ri[k].x, ri[k].x, s);
                s = fmaf(ri[k].y, ri[k].y, s);
                s = fmaf(ri[k].z, ri[k].z, s);
                s = fmaf(ri[k].w, ri[k].w, s);
            }
            s = wred(s);
            if (!lane) rn[i] = rsqrtf(fmaxf(s, 1e-16f));
#pragma unroll 1
            for (int j = i + 1; j < 14; j++) {
                float sj = 0.f;
#pragma unroll
                for (int k = 0; k < 8; k++) {
                    float4 vj = hs4[j * 256 + lane + 32 * k];
                    sj = fmaf(ri[k].x, vj.x, sj);
                    sj = fmaf(ri[k].y, vj.y, sj);
                    sj = fmaf(ri[k].z, vj.z, sj);
                    sj = fmaf(ri[k].w, vj.w, sj);
                }
                sj = wred(sj);
                if (!lane) cmat[i * 14 + j] = sj;
            }
        }
    }
    __syncthreads();

    float val = 0.f;
    if (tid < 196) {
        int i = tid / 14, j = tid % 14;
        if (i == j) val = 1.f;
        else {
            int lo = i < j ? i : j, hi = i < j ? j : i;
            val = fabsf(cmat[lo * 14 + hi] * rn[i] * rn[j]);
        }
    }
    __syncthreads();
    if (tid < 196) cmat[tid] = val;
    __syncthreads();
    if (tid < 14) {
        float s = 0.f;
        for (int j = 0; j < 14; j++) s += cmat[tid * 14 + j];
        dd[tid] = 1.f / sqrtf(fmaxf(s, 1.f));
    }
    __syncthreads();
    if (tid < 196) {
        int i = tid / 14, j = tid % 14;
        corr_out[(size_t)b * 196 + tid] = cmat[tid];
        g_corrn[(size_t)b * 196 + tid] = dd[i] * cmat[tid] * dd[j];
    }
}

// ------------------------- branch-1 aggregation + BN stats -------------------
__global__ __launch_bounds__(128) void agg1_kernel(const float* __restrict__ b1,
                                                   double* __restrict__ part) {
    const int b = blockIdx.x, tid = threadIdx.x, lane = tid & 31, warp = tid >> 5;
    __shared__ float sh[14 * 512];
    __shared__ float sA1[196], sA2[196];
    __shared__ float red[4][14][4];
    for (int t = tid; t < 196; t += 128) { sA1[t] = g_A1n[t]; sA2[t] = g_A2n[t]; }
    const float4* src = (const float4*)(g_xw1 + (size_t)b * 7168);
    float4* d4 = (float4*)sh;
#pragma unroll
    for (int k = 0; k < 14; k++) d4[tid + k * 128] = src[tid + k * 128];
    __syncthreads();
    float biasv[4];
#pragma unroll
    for (int t = 0; t < 4; t++) biasv[t] = b1[tid + t * 128];
    float* p1 = g_pre1 + (size_t)b * 7168;
    float* p3 = g_pre1 + (size_t)MROWS * 512 + (size_t)b * 7168;
#pragma unroll 1
    for (int i = 0; i < 14; i++) {
        float w1[14], w2[14];
#pragma unroll
        for (int j = 0; j < 14; j++) { w1[j] = sA1[i * 14 + j]; w2[j] = sA2[i * 14 + j]; }
        float s1 = 0, q1 = 0, s3 = 0, q3 = 0;
#pragma unroll
        for (int t = 0; t < 4; t++) {
            int c = tid + t * 128;
            float a1 = biasv[t], a3 = biasv[t];
#pragma unroll
            for (int j = 0; j < 14; j++) {
                float v = sh[j * 512 + c];
                a1 = fmaf(w1[j], v, a1);
                a3 = fmaf(w2[j], v, a3);
            }
            p1[i * 512 + c] = a1;
            p3[i * 512 + c] = a3;
            s1 += a1; q1 = fmaf(a1, a1, q1);
            s3 += a3; q3 = fmaf(a3, a3, q3);
        }
        s1 = wred(s1); q1 = wred(q1); s3 = wred(s3); q3 = wred(q3);
        if (!lane) { red[0][i][warp] = s1; red[1][i][warp] = q1; red[2][i][warp] = s3; red[3][i][warp] = q3; }
    }
    __syncthreads();
    if (tid < 28) {
        int node = tid % 14, st = tid / 14;
        double v1 = (double)red[st][node][0] + red[st][node][1] + red[st][node][2] + red[st][node][3];
        double v3 = (double)red[st + 2][node][0] + red[st + 2][node][1] + red[st + 2][node][2] + red[st + 2][node][3];
        part[(((size_t)0 * BATCH + b) * 14 + node) * 2 + st] = v1;
        part[(((size_t)1 * BATCH + b) * 14 + node) * 2 + st] = v3;
    }
}

// ------------------------- branch-2 aggregation (stats / write) --------------
// v2: each element loaded ONCE into registers; adjacency via smem broadcast.
template <bool WRITE>
__global__ __launch_bounds__(256) void agg2_kernel(const float* __restrict__ b2,
                                                   double* __restrict__ part,
                                                   float* __restrict__ out) {
    const int b = blockIdx.x, tid = threadIdx.x, lane = tid & 31, warp = tid >> 5;
    __shared__ float sadj[196];
    __shared__ float sscale[2][14], sshift[2][14];
    __shared__ float red[4][14][8];
    if (tid < 196) sadj[tid] = g_corrn[(size_t)b * 196 + tid];
    if (WRITE && tid < 28) {
        int s = tid / 14, n = tid % 14;
        sscale[s][n] = g_scale[2 + s][n];
        sshift[s][n] = g_shift[2 + s][n];
    }
    __syncthreads();
    const float* xb = g_xw2 + (size_t)b * 14336;
    const float* xa = g_xw2 + (size_t)MROWS * 1024 + (size_t)b * 14336;

    float s2a[14], q2a[14], s4a[14], q4a[14];
    if (!WRITE) {
#pragma unroll
        for (int i = 0; i < 14; i++) { s2a[i] = 0; q2a[i] = 0; s4a[i] = 0; q4a[i] = 0; }
    }

#pragma unroll 1
    for (int t = 0; t < 4; t++) {
        const int c = tid + t * 256;
        float v2r[14], v4r[14];
#pragma unroll
        for (int j = 0; j < 14; j++) {
            v2r[j] = __ldg(xb + j * 1024 + c);
            v4r[j] = __ldg(xa + j * 1024 + c);
        }
        const float bv = __ldg(b2 + c);
#pragma unroll
        for (int i = 0; i < 14; i++) {
            float a2 = bv, a4 = bv;
#pragma unroll
            for (int j = 0; j < 14; j++) {
                float w = sadj[i * 14 + j];
                a2 = fmaf(w, v2r[j], a2);
                a4 = fmaf(w, v4r[j], a4);
            }
            if (WRITE) {
                out[((size_t)b * 14 + i) * 1024 + c] =
                    lrelu(fmaf(a2, sscale[0][i], sshift[0][i])) +
                    lrelu(fmaf(a4, sscale[1][i], sshift[1][i]));
            } else {
                s2a[i] += a2; q2a[i] = fmaf(a2, a2, q2a[i]);
                s4a[i] += a4; q4a[i] = fmaf(a4, a4, q4a[i]);
            }
        }
    }

    if (!WRITE) {
#pragma unroll 1
        for (int i = 0; i < 14; i++) {
            float s2 = wred(s2a[i]), q2 = wred(q2a[i]);
            float s4 = wred(s4a[i]), q4 = wred(q4a[i]);
            if (!lane) { red[0][i][warp] = s2; red[1][i][warp] = q2; red[2][i][warp] = s4; red[3][i][warp] = q4; }
        }
        __syncthreads();
        if (tid < 28) {
            int node = tid % 14, st = tid / 14;
            double v2 = 0, v4 = 0;
#pragma unroll
            for (int wq = 0; wq < 8; wq++) {
                v2 += (double)red[st][node][wq];
                v4 += (double)red[st + 2][node][wq];
            }
            part[(((size_t)2 * BATCH + b) * 14 + node) * 2 + st] = v2;
            part[(((size_t)3 * BATCH + b) * 14 + node) * 2 + st] = v4;
        }
    }
}

// ------------------------- deterministic BN reduce ---------------------------
__global__ __launch_bounds__(1024) void bn_reduce_kernel(
    int setA, int setB, const float* __restrict__ gA, const float* __restrict__ bA,
    const float* __restrict__ gB, const float* __restrict__ bB,
    double invCount, const double* __restrict__ part) {
    __shared__ double chunk[56][32];
    const int tid = threadIdx.x;
    for (int task = tid; task < 1792; task += 1024) {
        int series = task >> 5, ch = task & 31;
        int set = (series < 28) ? setA : setB;
        int rem = series % 28;
        int node = rem >> 1, st = rem & 1;
        double s = 0;
        int b0 = ch * 128;
        for (int bb = 0; bb < 128; bb++)
            s += part[(((size_t)set * BATCH + b0 + bb) * 14 + node) * 2 + st];
        chunk[series][ch] = s;
    }
    __syncthreads();
    if (tid < 28) {
        int setidx = tid / 14, node = tid % 14;
        int set = setidx ? setB : setA;
        double S = 0, Q = 0;
        for (int ch = 0; ch < 32; ch++) {
            S += chunk[setidx * 28 + node * 2 + 0][ch];
            Q += chunk[setidx * 28 + node * 2 + 1][ch];
        }
        double mean = S * invCount;
        double var = Q * invCount - mean * mean;
        const float* g = setidx ? gB : gA;
        const float* be = setidx ? bB : bA;
        double sc = (double)g[node] / sqrt(var + 1e-5);
        g_scale[set][node] = (float)sc;
        g_shift[set][node] = (float)((double)be[node] - mean * sc);
    }
}

// ------------------------- host launcher -------------------------------------
static void* sym_addr(const void* sym) {
    void* p = nullptr;
    cudaGetSymbolAddress(&p, sym);
    return p;
}

extern "C" void kernel_launch(void* const* d_in, const int* in_sizes, int n_in,
                              void* d_out, int out_size) {
    const float* x     = (const float*)d_in[0];
    const float* adj1  = (const float*)d_in[1];
    const float* adj2  = (const float*)d_in[2];
    const float* fc_w  = (const float*)d_in[3];
    const float* fc_b  = (const float*)d_in[4];
    const float* g1w   = (const float*)d_in[5];
    const float* g1b   = (const float*)d_in[6];
    const float* g2w   = (const float*)d_in[7];
    const float* g2b   = (const float*)d_in[8];
    const float* gamma1 = (const float*)d_in[9];
    const float* beta1  = (const float*)d_in[10];
    const float* gamma2 = (const float*)d_in[11];
    const float* beta2  = (const float*)d_in[12];
    const float* gamma3 = (const float*)d_in[13];
    const float* beta3  = (const float*)d_in[14];

    float* out      = (float*)d_out;
    float* corr_out = out + OFF_CORR;
    float* h_out    = out + OFF_H;

    __half* p_wfch = (__half*)sym_addr(g_wfc_h);
    __half* p_wfcl = (__half*)sym_addr(g_wfc_l);
    __half* p_w1h  = (__half*)sym_addr(g_w1_h);
    __half* p_w1l  = (__half*)sym_addr(g_w1_l);
    __half* p_w2h  = (__half*)sym_addr(g_w2_h);
    __half* p_w2l  = (__half*)sym_addr(g_w2_l);
    float*  p_xw1  = (float*)sym_addr(g_xw1);
    float*  p_pre1 = (float*)sym_addr(g_pre1);
    float*  p_xw2  = (float*)sym_addr(g_xw2);
    double* p_part = (double*)sym_addr(g_part);

    const int SM1 = 2 * (A_SZ + B_SZ);       // 61440  (1-term)
    const int CORR_SM = 14 * 1024 * 4;       // 57344

    cudaFuncSetAttribute(hgemm2_k<1024, 1024, false, true,  1, false>, cudaFuncAttributeMaxDynamicSharedMemorySize, SM1);
    cudaFuncSetAttribute(hgemm2_k<1024,  512, false, false, 1, false>, cudaFuncAttributeMaxDynamicSharedMemorySize, SM1);
    cudaFuncSetAttribute(hgemm2_k< 512, 1024, true,  false, 1, true >, cudaFuncAttributeMaxDynamicSharedMemorySize, SM1);
    cudaFuncSetAttribute(corr_kernel, cudaFuncAttributeMaxDynamicSharedMemorySize, CORR_SM);

    prep_adj<<<1, 196>>>(adj1, adj2);

    wsplit_k<<<(1024 * 1024 + 255) / 256, 256>>>(fc_w, p_wfch, p_wfcl, 1024, 1024);
    wsplit_k<<<(512 * 1024 + 255) / 256, 256>>>(g1w, p_w1h, p_w1l, 1024, 512);
    wsplit_k<<<(1024 * 512 + 255) / 256, 256>>>(g2w, p_w2h, p_w2l, 512, 1024);

    // h = lrelu(x @ fc_w + fc_b)   (1-term)
    hgemm2_k<1024, 1024, false, true, 1, false><<<dim3(4, 448), 256, SM1>>>(x, p_wfch, p_wfcl, fc_b, h_out, 0);
    corr_kernel<<<BATCH, 256, CORR_SM>>>(h_out, corr_out);

    // xw1 = x @ gcn1_w   (1-term)
    hgemm2_k<1024, 512, false, false, 1, false><<<dim3(2, 448), 256, SM1>>>(x, p_w1h, p_w1l, nullptr, p_xw1, 0);
    agg1_kernel<<<BATCH, 128>>>(g1b, p_part);
    bn_reduce_kernel<<<1, 1024>>>(0, 1, gamma1, beta1, gamma3, beta3,
                                  1.0 / ((double)BATCH * HID), p_part);

    // stacked gcn2 GEMM: by<448 -> pre1/preset0, by>=448 -> pre3/preset1
    hgemm2_k<512, 1024, true, false, 1, true><<<dim3(4, 896), 256, SM1>>>(p_pre1, p_w2h, p_w2l, nullptr, p_xw2, 0);

    agg2_kernel<false><<<BATCH, 256>>>(g2b, p_part, nullptr);
    bn_reduce_kernel<<<1, 1024>>>(2, 3, gamma2, beta2, gamma2, beta2,
                                  1.0 / ((double)BATCH * FOUT), p_part);
    agg2_kernel<true><<<BATCH, 256>>>(g2b, p_part, out);

    (void)in_sizes; (void)n_in; (void)out_size;
}